// round 12
// baseline (speedup 1.0000x reference)
#include <cuda_runtime.h>
#include <cuda_bf16.h>
#include <cuda_fp16.h>
#include <cstdint>

#define BB 16
#define TT 512
#define LL 128
#define NSTEP 129
#define ENCD 512
#define HD 1024
#define ED 512
#define VD 10000
#define AD 512

#define NBLK 148
#define NTHR 512
#define NWARP (NBLK * (NTHR / 32))

typedef unsigned long long u64;

// ---- scratch (device globals; allocs are forbidden) ----
__device__ float g_encproj[(size_t)BB * TT * AD];
__device__ float g_h0[2][BB * HD];
__device__ float g_h1[2][BB * HD];
__device__ float g_c0[BB * HD];
__device__ float g_c1[BB * HD];
__device__ float g_ctx[2][BB * ENCD];
__device__ float g_dproj[BB * AD];
__device__ float g_aw[BB * TT];
__device__ float g_awsum[BB];
__device__ float g_dcat[(size_t)NSTEP * BB * 1536];
__device__ unsigned g_bar;
__device__ volatile unsigned g_gen;

// fp16 LSTM weights (L2-resident working set)
#define WSZ ((size_t)4096 * 1024)
__device__ __half g_Wih0h[WSZ];
__device__ __half g_Whh0h[WSZ];
__device__ __half g_Wih1h[WSZ];
__device__ __half g_Whh1h[WSZ];

// bf16 split buffers for tensor-core logits GEMM
#define MROWS 2176
#define NPAD 10048
__device__ __nv_bfloat16 g_Ahi[(size_t)MROWS * HD];
__device__ __nv_bfloat16 g_Alo[(size_t)MROWS * HD];
__device__ __nv_bfloat16 g_Bhi[(size_t)HD * NPAD];
__device__ __nv_bfloat16 g_Blo[(size_t)HD * NPAD];

__device__ __forceinline__ float sigf(float x) { return __fdividef(1.f, 1.f + __expf(-x)); }
__device__ __forceinline__ float tanhf_fast(float x) {
    float z = __expf(2.f * x);
    return 1.f - __fdividef(2.f, z + 1.f);
}
__device__ __forceinline__ float tanh_apx(float x) {
    float r; asm("tanh.approx.f32 %0, %1;" : "=f"(r) : "f"(x)); return r;
}

// packed f32x2 helpers
__device__ __forceinline__ void fma2(u64& acc, u64 a, u64 b) {
    asm("fma.rn.f32x2 %0, %1, %2, %0;" : "+l"(acc) : "l"(a), "l"(b));
}
__device__ __forceinline__ u64 add2(u64 a, u64 b) {
    u64 r; asm("add.rn.f32x2 %0, %1, %2;" : "=l"(r) : "l"(a), "l"(b)); return r;
}
__device__ __forceinline__ u64 pack2(float lo, float hi) {
    u64 r; asm("mov.b64 %0, {%1, %2};" : "=l"(r) : "f"(lo), "f"(hi)); return r;
}
__device__ __forceinline__ void unpack2(u64 v, float& lo, float& hi) {
    asm("mov.b64 {%0, %1}, %2;" : "=f"(lo), "=f"(hi) : "l"(v));
}

// fp16x4 weight load via L2 (.cg), convert to float4
__device__ __forceinline__ float4 ldw_h(const __half* p) {
    uint2 v = __ldcg((const uint2*)p);
    float2 f0 = __half22float2(*(__half2*)&v.x);
    float2 f1 = __half22float2(*(__half2*)&v.y);
    return make_float4(f0.x, f0.y, f1.x, f1.y);
}

// R5-proven barrier
__device__ __forceinline__ void grid_sync(unsigned& mygen) {
    __syncthreads();
    if (threadIdx.x == 0) {
        unsigned tgt = mygen + 1u;
        __threadfence();
        if (atomicAdd(&g_bar, 1u) == NBLK - 1) {
            g_bar = 0u;
            __threadfence();
            g_gen = tgt;
        } else {
            while (g_gen < tgt) { __nanosleep(64); }
            __threadfence();
        }
    }
    mygen += 1u;
    __syncthreads();
}

// u64 packed-pair butterfly: afterwards lane l holds (in acc[0]) packed totals of index l
#define RSTAGE2(OFF, HALF) \
    { bool hi = (lane & OFF) != 0; \
      _Pragma("unroll") \
      for (int i = 0; i < HALF; ++i) { \
          u64 o0 = __shfl_xor_sync(0xffffffffu, acc[i], OFF); \
          u64 o1 = __shfl_xor_sync(0xffffffffu, acc[i + HALF], OFF); \
          acc[i] = hi ? add2(acc[i + HALF], o1) : add2(acc[i], o0); \
      } }

__global__ void init_kernel() {
    int i = blockIdx.x * blockDim.x + threadIdx.x;
    if (i < BB * HD) { g_h0[0][i] = 0.f; g_c0[i] = 0.f; g_h1[0][i] = 0.f; g_c1[i] = 0.f; }
    if (i < BB * ENCD) g_ctx[0][i] = 0.f;
    if (i == 0) { g_bar = 0u; g_gen = 0u; }
    for (size_t j = i; j < (size_t)(MROWS - 2064) * HD; j += (size_t)16384) {
        g_Ahi[(size_t)2064 * HD + j] = __float2bfloat16(0.f);
        g_Alo[(size_t)2064 * HD + j] = __float2bfloat16(0.f);
    }
}

__global__ void conv_w_kernel(const float* __restrict__ W0, const float* __restrict__ W1,
                              const float* __restrict__ W2, const float* __restrict__ W3) {
    size_t i = (size_t)blockIdx.x * blockDim.x + threadIdx.x;
    if (i >= WSZ) return;
    g_Wih0h[i] = __float2half(W0[i]);
    g_Whh0h[i] = __float2half(W1[i]);
    g_Wih1h[i] = __float2half(W2[i]);
    g_Whh1h[i] = __float2half(W3[i]);
}

// ======================= persistent recurrent kernel =========================
// One job per unit u (1024 jobs/layer); warp computes 4 gates x 16 batches as
// packed batch-pairs with fma.rn.f32x2. Weight read ONCE per step.
template<int LAYER>
__device__ __forceinline__ void lstm_pass(
    int t, int gw, int lane,
    const int* __restrict__ ys, const float* __restrict__ embed,
    const __half* __restrict__ Wih, const __half* __restrict__ Whh,
    const float* __restrict__ bi,
    const float* __restrict__ ctx,
    const float* __restrict__ hprev,
    const float* __restrict__ h0new,
    float* __restrict__ cbuf, float* __restrict__ hout)
{
    for (int u = gw; u < 1024; u += NWARP) {
        int tok[8];   // LAYER0: tokens for batch pairs handled on the fly (2 per pair)
        if (LAYER == 0) {
            #pragma unroll
            for (int b = 0; b < 8; ++b) {
                // store token pair packed in two halves of consecutive ints handled below
                tok[b] = 0;
            }
        }
        u64 acc[32];  // acc[g*8+bp] = packed (batch 2bp, batch 2bp+1)
        #pragma unroll
        for (int i = 0; i < 32; ++i) acc[i] = 0ull;

        // ---- segment 0: W_ih ----
        #pragma unroll
        for (int c = 0; c < 8; ++c) {
            const int k0 = c * 128 + lane * 4;
            u64 wd[4][4];
            #pragma unroll
            for (int g = 0; g < 4; ++g) {
                float4 w = ldw_h(Wih + (size_t)(u + g * HD) * 1024 + k0);
                wd[g][0] = pack2(w.x, w.x); wd[g][1] = pack2(w.y, w.y);
                wd[g][2] = pack2(w.z, w.z); wd[g][3] = pack2(w.w, w.w);
            }
            #pragma unroll
            for (int bp = 0; bp < 8; ++bp) {
                const float *pa, *pb;
                if (LAYER == 0) {
                    if (c < 4) {
                        const int ta = (t == 0) ? 1 : ys[(2 * bp) * LL + (t - 1)];
                        const int tb = (t == 0) ? 1 : ys[(2 * bp + 1) * LL + (t - 1)];
                        pa = embed + (size_t)ta * ED + k0;
                        pb = embed + (size_t)tb * ED + k0;
                    } else {
                        pa = ctx + (2 * bp) * ENCD + (k0 - 512);
                        pb = ctx + (2 * bp + 1) * ENCD + (k0 - 512);
                    }
                } else {
                    pa = h0new + (2 * bp) * HD + k0;
                    pb = h0new + (2 * bp + 1) * HD + k0;
                }
                float4 xa = *(const float4*)pa;
                float4 xb = *(const float4*)pb;
                u64 x0 = pack2(xa.x, xb.x), x1 = pack2(xa.y, xb.y);
                u64 x2 = pack2(xa.z, xb.z), x3 = pack2(xa.w, xb.w);
                #pragma unroll
                for (int g = 0; g < 4; ++g) {
                    fma2(acc[g * 8 + bp], x0, wd[g][0]);
                    fma2(acc[g * 8 + bp], x1, wd[g][1]);
                    fma2(acc[g * 8 + bp], x2, wd[g][2]);
                    fma2(acc[g * 8 + bp], x3, wd[g][3]);
                }
            }
        }
        // ---- segment 1: W_hh ----
        #pragma unroll
        for (int c = 0; c < 8; ++c) {
            const int k0 = c * 128 + lane * 4;
            u64 wd[4][4];
            #pragma unroll
            for (int g = 0; g < 4; ++g) {
                float4 w = ldw_h(Whh + (size_t)(u + g * HD) * 1024 + k0);
                wd[g][0] = pack2(w.x, w.x); wd[g][1] = pack2(w.y, w.y);
                wd[g][2] = pack2(w.z, w.z); wd[g][3] = pack2(w.w, w.w);
            }
            #pragma unroll
            for (int bp = 0; bp < 8; ++bp) {
                float4 xa = *(const float4*)(hprev + (2 * bp) * HD + k0);
                float4 xb = *(const float4*)(hprev + (2 * bp + 1) * HD + k0);
                u64 x0 = pack2(xa.x, xb.x), x1 = pack2(xa.y, xb.y);
                u64 x2 = pack2(xa.z, xb.z), x3 = pack2(xa.w, xb.w);
                #pragma unroll
                for (int g = 0; g < 4; ++g) {
                    fma2(acc[g * 8 + bp], x0, wd[g][0]);
                    fma2(acc[g * 8 + bp], x1, wd[g][1]);
                    fma2(acc[g * 8 + bp], x2, wd[g][2]);
                    fma2(acc[g * 8 + bp], x3, wd[g][3]);
                }
            }
        }

        RSTAGE2(16, 16) RSTAGE2(8, 8) RSTAGE2(4, 4) RSTAGE2(2, 2) RSTAGE2(1, 1)
        // lane l holds packed totals for index l = g*8 + bp
        const u64 v = acc[0];
        const int bp = (lane & 15) >> 1;
        u64 pi = __shfl_sync(0xffffffffu, v, bp);
        u64 pf = __shfl_sync(0xffffffffu, v, bp + 8);
        u64 pg = __shfl_sync(0xffffffffu, v, bp + 16);
        u64 po = __shfl_sync(0xffffffffu, v, bp + 24);
        if (lane < 16) {
            const int b = lane;
            float ilo, ihi, flo, fhi, glo, ghi, olo, ohi;
            unpack2(pi, ilo, ihi); unpack2(pf, flo, fhi);
            unpack2(pg, glo, ghi); unpack2(po, olo, ohi);
            const int sel = b & 1;
            float si_ = (sel ? ihi : ilo) + bi[u];
            float sf_ = (sel ? fhi : flo) + bi[u + HD];
            float sg_ = (sel ? ghi : glo) + bi[u + 2 * HD];
            float so_ = (sel ? ohi : olo) + bi[u + 3 * HD];
            const int idx = b * HD + u;
            float c = sigf(sf_) * cbuf[idx] + sigf(si_) * tanhf_fast(sg_);
            cbuf[idx] = c;
            float h = sigf(so_) * tanhf_fast(c);
            hout[idx] = h;
            if (LAYER == 1)
                g_dcat[((size_t)t * BB + b) * 1536 + u] = h + h0new[idx];
        }
    }
}

__global__ __launch_bounds__(NTHR, 1) void dec_persistent(
    const float* __restrict__ enc_out, const int* __restrict__ enc_lens,
    const int* __restrict__ ys, const float* __restrict__ embed,
    const float* __restrict__ bi0, const float* __restrict__ bi1,
    const float* __restrict__ Wdec, const float* __restrict__ vatt)
{
    const int lane = threadIdx.x & 31;
    const int gw = blockIdx.x * (NTHR / 32) + (threadIdx.x >> 5);
    const int gt = blockIdx.x * NTHR + threadIdx.x;
    unsigned mygen = 0;

    for (int t = 0; t < NSTEP; ++t) {
        const int par = t & 1;
        const float* h0r = g_h0[par];
        float* h0w = g_h0[par ^ 1];
        const float* h1r = g_h1[par];
        float* h1w = g_h1[par ^ 1];
        const float* ctxr = g_ctx[par];
        float* ctxw = g_ctx[par ^ 1];

        lstm_pass<0>(t, gw, lane, ys, embed, g_Wih0h, g_Whh0h, bi0, ctxr, h0r, h0w, g_c0, h0w);
        if (gt < BB * AD) g_dproj[gt] = 0.f;
        grid_sync(mygen);

        lstm_pass<1>(t, gw, lane, ys, embed, g_Wih1h, g_Whh1h, bi1, ctxr, h1r, h0w, g_c1, h1w);
        if (gt < BB * ENCD) {
            ctxw[gt] = 0.f;
            g_dcat[((size_t)t * BB + (gt >> 9)) * 1536 + 1024 + (gt & 511)] = 0.f;
        }
        if (gt < BB) g_awsum[gt] = 0.f;
        grid_sync(mygen);

        for (int job = gw; job < 2048; job += NWARP) {
            const int b = job >> 7;
            const int cg = (job >> 3) & 15;
            const int ks = job & 7;
            const int a0 = cg << 5;
            const float* dec = g_dcat + ((size_t)t * BB + b) * 1536 + ks * 128;
            const float* w = Wdec + (size_t)(ks * 128) * AD + a0 + lane;
            float s0 = 0.f, s1 = 0.f, s2 = 0.f, s3 = 0.f;
            #pragma unroll 8
            for (int k = 0; k < 128; k += 4) {
                s0 = fmaf(dec[k], w[(size_t)k * AD], s0);
                s1 = fmaf(dec[k + 1], w[(size_t)(k + 1) * AD], s1);
                s2 = fmaf(dec[k + 2], w[(size_t)(k + 2) * AD], s2);
                s3 = fmaf(dec[k + 3], w[(size_t)(k + 3) * AD], s3);
            }
            atomicAdd(&g_dproj[b * AD + a0 + lane], (s0 + s1) + (s2 + s3));
        }
        grid_sync(mygen);

        for (int job = gw; job < BB * TT; job += NWARP) {
            const int b = job >> 9, tt = job & (TT - 1);
            const float4* p4 = (const float4*)(g_encproj + (size_t)(b * TT + tt) * AD);
            const float4* d4 = (const float4*)(g_dproj + b * AD);
            const float4* v4 = (const float4*)vatt;
            float s = 0.f;
            #pragma unroll
            for (int i = lane; i < AD / 4; i += 32) {
                float4 p = __ldcs(p4 + i); float4 d = d4[i]; float4 vv = v4[i];
                s = fmaf(vv.x, tanh_apx(p.x + d.x), s);
                s = fmaf(vv.y, tanh_apx(p.y + d.y), s);
                s = fmaf(vv.z, tanh_apx(p.z + d.z), s);
                s = fmaf(vv.w, tanh_apx(p.w + d.w), s);
            }
            #pragma unroll
            for (int off = 16; off > 0; off >>= 1) s += __shfl_xor_sync(0xffffffffu, s, off);
            if (lane == 0) {
                float w = (tt < enc_lens[b]) ? __expf(s) : 0.f;
                g_aw[b * TT + tt] = w;
                if (w != 0.f) atomicAdd(&g_awsum[b], w);
            }
        }
        grid_sync(mygen);

        for (int job = gw; job < 2048; job += NWARP) {
            const int b = job >> 7;
            const int cg = (job >> 3) & 15;
            const int ts = job & 7;
            const int col = (cg << 5) + lane;
            const float inv = __fdividef(1.f, g_awsum[b]);
            const float* ao = g_aw + b * TT + ts * 64;
            const float* eo = enc_out + (size_t)b * TT * ENCD + (size_t)(ts * 64) * ENCD + col;
            float s0 = 0.f, s1 = 0.f;
            #pragma unroll 8
            for (int tt = 0; tt < 64; tt += 2) {
                s0 = fmaf(ao[tt], __ldcs(eo + (size_t)tt * ENCD), s0);
                s1 = fmaf(ao[tt + 1], __ldcs(eo + (size_t)(tt + 1) * ENCD), s1);
            }
            float cv = (s0 + s1) * inv;
            atomicAdd(&ctxw[b * ENCD + col], cv);
            atomicAdd(&g_dcat[((size_t)t * BB + b) * 1536 + 1024 + col], cv);
        }
        grid_sync(mygen);
    }
}

// ---- tiled fp32 GEMM (FFMA2). mode 0: plain; mode 3: tanh + bf16 hi/lo split ----
#define GBM 128
#define GBN 64
#define GBK 16

__global__ __launch_bounds__(256) void gemm_kernel(
    const float* __restrict__ Am, const float* __restrict__ Bm,
    const float* __restrict__ bias, float* __restrict__ Cm,
    int M, int N, int K, int mode)
{
    __shared__ float As[GBK][GBM + 4];
    __shared__ float Bs[GBK][GBN];
    const int tid = threadIdx.x;
    const int tx = tid & 15, ty = tid >> 4;
    const int n0 = blockIdx.x * GBN;
    const int m0 = blockIdx.y * GBM;
    u64 acc2[8][2];
    #pragma unroll
    for (int r = 0; r < 8; r++) { acc2[r][0] = 0ull; acc2[r][1] = 0ull; }

    for (int k0 = 0; k0 < K; k0 += GBK) {
        #pragma unroll
        for (int i = tid; i < (GBM * GBK) / 4; i += 256) {
            int row = i >> 2, kq = (i & 3) << 2;
            float4 v = make_float4(0.f, 0.f, 0.f, 0.f);
            int gm = m0 + row;
            if (gm < M) v = *(const float4*)(Am + (size_t)gm * K + k0 + kq);
            As[kq][row] = v.x; As[kq + 1][row] = v.y; As[kq + 2][row] = v.z; As[kq + 3][row] = v.w;
        }
        {
            int row = tid >> 4, nq = (tid & 15) << 2;
            float4 v = make_float4(0.f, 0.f, 0.f, 0.f);
            if (n0 + nq < N) v = *(const float4*)(Bm + (size_t)(k0 + row) * N + n0 + nq);
            *(float4*)&Bs[row][nq] = v;
        }
        __syncthreads();
        #pragma unroll
        for (int k = 0; k < GBK; k++) {
            float4 bv = *(const float4*)&Bs[k][tx << 2];
            u64 b01 = pack2(bv.x, bv.y);
            u64 b23 = pack2(bv.z, bv.w);
            #pragma unroll
            for (int r = 0; r < 8; r++) {
                float a = As[k][(ty << 3) + r];
                u64 aa = pack2(a, a);
                fma2(acc2[r][0], aa, b01);
                fma2(acc2[r][1], aa, b23);
            }
        }
        __syncthreads();
    }
    #pragma unroll
    for (int r = 0; r < 8; r++) {
        int m = m0 + (ty << 3) + r;
        if (m >= M) continue;
        float av[4];
        unpack2(acc2[r][0], av[0], av[1]);
        unpack2(acc2[r][1], av[2], av[3]);
        #pragma unroll
        for (int c = 0; c < 4; c++) {
            int n = n0 + (tx << 2) + c;
            if (n >= N) continue;
            float v = av[c] + bias[n];
            if (mode == 3) {
                v = tanhf_fast(v);
                __nv_bfloat16 h = __float2bfloat16(v);
                g_Ahi[(size_t)m * HD + n] = h;
                g_Alo[(size_t)m * HD + n] = __float2bfloat16(v - __bfloat162float(h));
            } else {
                Cm[(size_t)m * N + n] = v;
            }
        }
    }
}

// ---- W_out elementwise bf16 hi/lo split ----
__global__ void conv_wout_kernel(const float* __restrict__ W) {
    size_t i = (size_t)blockIdx.x * blockDim.x + threadIdx.x;
    if (i >= (size_t)HD * NPAD) return;
    int k = (int)(i / NPAD), n = (int)(i % NPAD);
    float v = (n < VD) ? W[(size_t)k * VD + n] : 0.f;
    __nv_bfloat16 h = __float2bfloat16(v);
    g_Bhi[i] = h;
    g_Blo[i] = __float2bfloat16(v - __bfloat162float(h));
}

// ======================= mma.sync bf16 split-precision logits GEMM =============
__device__ __forceinline__ uint32_t smem_u32(const void* p) {
    uint32_t a;
    asm("{ .reg .u64 t; cvta.to.shared.u64 t, %1; cvt.u32.u64 %0, t; }" : "=r"(a) : "l"(p));
    return a;
}
__device__ __forceinline__ void ldmA4(uint32_t* r, uint32_t addr) {
    asm volatile("ldmatrix.sync.aligned.m8n8.x4.shared.b16 {%0,%1,%2,%3}, [%4];"
                 : "=r"(r[0]), "=r"(r[1]), "=r"(r[2]), "=r"(r[3]) : "r"(addr));
}
__device__ __forceinline__ void ldmBT2(uint32_t* r, uint32_t addr) {
    asm volatile("ldmatrix.sync.aligned.m8n8.x2.trans.shared.b16 {%0,%1}, [%2];"
                 : "=r"(r[0]), "=r"(r[1]) : "r"(addr));
}
__device__ __forceinline__ void mma16816(float* d, const uint32_t* a, const uint32_t* b) {
    asm volatile(
        "mma.sync.aligned.m16n8k16.row.col.f32.bf16.bf16.f32 "
        "{%0,%1,%2,%3}, {%4,%5,%6,%7}, {%8,%9}, {%0,%1,%2,%3};"
        : "+f"(d[0]), "+f"(d[1]), "+f"(d[2]), "+f"(d[3])
        : "r"(a[0]), "r"(a[1]), "r"(a[2]), "r"(a[3]), "r"(b[0]), "r"(b[1]));
}

#define ASTR 40
#define BSTR 72

__global__ __launch_bounds__(256) void wout_mma_kernel(const float* __restrict__ bias,
                                                       float* __restrict__ out)
{
    __shared__ __nv_bfloat16 sAh[128 * ASTR], sAl[128 * ASTR];
    __shared__ __nv_bfloat16 sBh[32 * BSTR], sBl[32 * BSTR];
    const int tid = threadIdx.x;
    const int lane = tid & 31;
    const int w = tid >> 5;
    const int mwarp = w & 3, nwarp = w >> 2;
    const int n0 = blockIdx.x * 64;
    const int m0 = blockIdx.y * 128;

    const uint32_t sAh_b = smem_u32(sAh), sAl_b = smem_u32(sAl);
    const uint32_t sBh_b = smem_u32(sBh), sBl_b = smem_u32(sBl);
    const uint32_t aoff = ((mwarp * 32 + (lane & 15)) * ASTR + (lane >> 4) * 8) * 2;
    const uint32_t boff = ((lane & 15) * BSTR + nwarp * 32) * 2;

    float d[2][4][4];
    #pragma unroll
    for (int mt = 0; mt < 2; ++mt)
        #pragma unroll
        for (int nt = 0; nt < 4; ++nt)
            #pragma unroll
            for (int i = 0; i < 4; ++i) d[mt][nt][i] = 0.f;

    for (int kc = 0; kc < 32; ++kc) {
        const int kb = kc * 32;
        #pragma unroll
        for (int i = tid; i < 512; i += 256) {
            const int row = i >> 2, kq = (i & 3) << 3;
            const size_t src = (size_t)(m0 + row) * HD + kb + kq;
            *(float4*)((char*)sAh + (row * ASTR + kq) * 2) = *(const float4*)(g_Ahi + src);
            *(float4*)((char*)sAl + (row * ASTR + kq) * 2) = *(const float4*)(g_Alo + src);
        }
        {
            const int row = tid >> 3, nq = (tid & 7) << 3;
            const size_t src = (size_t)(kb + row) * NPAD + n0 + nq;
            *(float4*)((char*)sBh + (row * BSTR + nq) * 2) = *(const float4*)(g_Bhi + src);
            *(float4*)((char*)sBl + (row * BSTR + nq) * 2) = *(const float4*)(g_Blo + src);
        }
        __syncthreads();

        #pragma unroll
        for (int ks = 0; ks < 2; ++ks) {
            uint32_t ah[2][4], al[2][4], bh[4][2], bl[4][2];
            #pragma unroll
            for (int mt = 0; mt < 2; ++mt) {
                const uint32_t o = aoff + (mt * 16 * ASTR + ks * 16) * 2;
                ldmA4(ah[mt], sAh_b + o);
                ldmA4(al[mt], sAl_b + o);
            }
            #pragma unroll
            for (int nt = 0; nt < 4; ++nt) {
                const uint32_t o = boff + (ks * 16 * BSTR + nt * 8) * 2;
                ldmBT2(bh[nt], sBh_b + o);
                ldmBT2(bl[nt], sBl_b + o);
            }
            #pragma unroll
            for (int mt = 0; mt < 2; ++mt)
                #pragma unroll
                for (int nt = 0; nt < 4; ++nt) {
                    mma16816(d[mt][nt], ah[mt], bh[nt]);
                    mma16816(d[mt][nt], ah[mt], bl[nt]);
                    mma16816(d[mt][nt], al[mt], bh[nt]);
                }
        }
        __syncthreads();
    }

    const int grp = lane >> 2, tig = lane & 3;
    #pragma unroll
    for (int mt = 0; mt < 2; ++mt) {
        #pragma unroll
        for (int rr = 0; rr < 2; ++rr) {
            const int m = m0 + mwarp * 32 + mt * 16 + grp + rr * 8;
            if (m >= NSTEP * BB) continue;
            const int bb = m & 15, tt = m >> 4;
            float* orow = out + ((size_t)bb * NSTEP + tt) * VD;
            #pragma unroll
            for (int nt = 0; nt < 4; ++nt) {
                const int n = n0 + nwarp * 32 + nt * 8 + tig * 2;
                if (n < VD) {
                    orow[n] = d[mt][nt][rr * 2 + 0] + bias[n];
                    orow[n + 1] = d[mt][nt][rr * 2 + 1] + bias[n + 1];
                }
            }
        }
    }
}

extern "C" void kernel_launch(void* const* d_in, const int* in_sizes, int n_in,
                              void* d_out, int out_size)
{
    const float* enc_out  = (const float*)d_in[0];
    const int*   enc_lens = (const int*)d_in[1];
    const int*   ys       = (const int*)d_in[2];
    const float* embed    = (const float*)d_in[3];
    const float* Wih0     = (const float*)d_in[4];
    const float* Whh0     = (const float*)d_in[5];
    const float* b0       = (const float*)d_in[6];
    const float* Wih1     = (const float*)d_in[7];
    const float* Whh1     = (const float*)d_in[8];
    const float* b1       = (const float*)d_in[9];
    const float* W_enc    = (const float*)d_in[10];
    const float* b_att    = (const float*)d_in[11];
    const float* v_att    = (const float*)d_in[12];
    const float* W_dec    = (const float*)d_in[13];
    const float* W_bn     = (const float*)d_in[14];
    const float* b_bn     = (const float*)d_in[15];
    const float* W_out    = (const float*)d_in[16];
    const float* b_out    = (const float*)d_in[17];
    float* out = (float*)d_out;

    float *p_encproj, *p_dcat;
    cudaGetSymbolAddress((void**)&p_encproj, g_encproj);
    cudaGetSymbolAddress((void**)&p_dcat, g_dcat);

    init_kernel<<<(BB * HD + 255) / 256, 256>>>();

    conv_w_kernel<<<(unsigned)((WSZ + 255) / 256), 256>>>(Wih0, Whh0, Wih1, Whh1);

    {
        size_t tot = (size_t)HD * NPAD;
        conv_wout_kernel<<<(unsigned)((tot + 255) / 256), 256>>>(W_out);
    }

    {
        dim3 grid(AD / GBN, (BB * TT + GBM - 1) / GBM);
        gemm_kernel<<<grid, 256>>>(enc_out, W_enc, b_att, p_encproj, BB * TT, AD, ENCD, 0);
    }

    dec_persistent<<<NBLK, NTHR>>>(enc_out, enc_lens, ys, embed, b0, b1, W_dec, v_att);

    {
        dim3 grid(HD / GBN, (NSTEP * BB + GBM - 1) / GBM);
        gemm_kernel<<<grid, 256>>>(p_dcat, W_bn, b_bn, p_dcat /*unused*/, NSTEP * BB, HD, 1536, 3);
    }

    {
        dim3 grid(NPAD / 64, MROWS / 128);
        wout_mma_kernel<<<grid, 256>>>(b_out, out);
    }
    (void)in_sizes; (void)n_in; (void)out_size;
}

// round 13
// speedup vs baseline: 1.9415x; 1.9415x over previous
#include <cuda_runtime.h>
#include <cuda_bf16.h>
#include <cuda_fp16.h>
#include <cstdint>

#define BB 16
#define TT 512
#define LL 128
#define NSTEP 129
#define ENCD 512
#define HD 1024
#define ED 512
#define VD 10000
#define AD 512

#define NBLK 148
#define NTHR 512
#define NWARP (NBLK * (NTHR / 32))

typedef unsigned long long u64;

// ---- scratch (device globals; allocs are forbidden) ----
__device__ float g_encproj[(size_t)BB * TT * AD];
__device__ float g_h0[2][BB * HD];
__device__ float g_h1[2][BB * HD];
__device__ float g_c0[BB * HD];
__device__ float g_c1[BB * HD];
__device__ float g_ctx[2][BB * ENCD];
__device__ float g_dproj[BB * AD];
__device__ float g_aw[BB * TT];
__device__ float g_awsum[BB];
__device__ float g_dcat[(size_t)NSTEP * BB * 1536];
__device__ unsigned g_bar;
__device__ volatile unsigned g_gen;

// fp16 LSTM weights (L2-resident working set)
#define WSZ ((size_t)4096 * 1024)
__device__ __half g_Wih0h[WSZ];
__device__ __half g_Whh0h[WSZ];
__device__ __half g_Wih1h[WSZ];
__device__ __half g_Whh1h[WSZ];

// bf16 split buffers for tensor-core logits GEMM
#define MROWS 2176
#define NPAD 10048
__device__ __nv_bfloat16 g_Ahi[(size_t)MROWS * HD];
__device__ __nv_bfloat16 g_Alo[(size_t)MROWS * HD];
__device__ __nv_bfloat16 g_Bhi[(size_t)HD * NPAD];
__device__ __nv_bfloat16 g_Blo[(size_t)HD * NPAD];

__device__ __forceinline__ float sigf(float x) { return __fdividef(1.f, 1.f + __expf(-x)); }
__device__ __forceinline__ float tanhf_fast(float x) {
    float z = __expf(2.f * x);
    return 1.f - __fdividef(2.f, z + 1.f);
}
__device__ __forceinline__ float tanh_apx(float x) {
    float r; asm("tanh.approx.f32 %0, %1;" : "=f"(r) : "f"(x)); return r;
}

// packed f32x2 helpers
__device__ __forceinline__ void fma2(u64& acc, u64 a, u64 b) {
    asm("fma.rn.f32x2 %0, %1, %2, %0;" : "+l"(acc) : "l"(a), "l"(b));
}
__device__ __forceinline__ u64 add2(u64 a, u64 b) {
    u64 r; asm("add.rn.f32x2 %0, %1, %2;" : "=l"(r) : "l"(a), "l"(b)); return r;
}
__device__ __forceinline__ u64 pack2(float lo, float hi) {
    u64 r; asm("mov.b64 %0, {%1, %2};" : "=l"(r) : "f"(lo), "f"(hi)); return r;
}
__device__ __forceinline__ void unpack2(u64 v, float& lo, float& hi) {
    asm("mov.b64 {%0, %1}, %2;" : "=f"(lo), "=f"(hi) : "l"(v));
}

// fp16x4 weight load via L2 (.cg), convert to float4
__device__ __forceinline__ float4 ldw_h(const __half* p) {
    uint2 v = __ldcg((const uint2*)p);
    float2 f0 = __half22float2(*(__half2*)&v.x);
    float2 f1 = __half22float2(*(__half2*)&v.y);
    return make_float4(f0.x, f0.y, f1.x, f1.y);
}

// R5-proven barrier
__device__ __forceinline__ void grid_sync(unsigned& mygen) {
    __syncthreads();
    if (threadIdx.x == 0) {
        unsigned tgt = mygen + 1u;
        __threadfence();
        if (atomicAdd(&g_bar, 1u) == NBLK - 1) {
            g_bar = 0u;
            __threadfence();
            g_gen = tgt;
        } else {
            while (g_gen < tgt) { __nanosleep(64); }
            __threadfence();
        }
    }
    mygen += 1u;
    __syncthreads();
}

// u64 packed butterfly stage over array acc[]
#define RSTAGE2(OFF, HALF) \
    { bool hi = (lane & OFF) != 0; \
      _Pragma("unroll") \
      for (int i = 0; i < HALF; ++i) { \
          u64 o0 = __shfl_xor_sync(0xffffffffu, acc[i], OFF); \
          u64 o1 = __shfl_xor_sync(0xffffffffu, acc[i + HALF], OFF); \
          acc[i] = hi ? add2(acc[i + HALF], o1) : add2(acc[i], o0); \
      } }

__global__ void init_kernel() {
    int i = blockIdx.x * blockDim.x + threadIdx.x;
    if (i < BB * HD) { g_h0[0][i] = 0.f; g_c0[i] = 0.f; g_h1[0][i] = 0.f; g_c1[i] = 0.f; }
    if (i < BB * ENCD) g_ctx[0][i] = 0.f;
    if (i == 0) { g_bar = 0u; g_gen = 0u; }
    for (size_t j = i; j < (size_t)(MROWS - 2064) * HD; j += (size_t)16384) {
        g_Ahi[(size_t)2064 * HD + j] = __float2bfloat16(0.f);
        g_Alo[(size_t)2064 * HD + j] = __float2bfloat16(0.f);
    }
}

__global__ void conv_w_kernel(const float* __restrict__ W0, const float* __restrict__ W1,
                              const float* __restrict__ W2, const float* __restrict__ W3) {
    size_t i = (size_t)blockIdx.x * blockDim.x + threadIdx.x;
    if (i >= WSZ) return;
    g_Wih0h[i] = __float2half(W0[i]);
    g_Whh0h[i] = __float2half(W1[i]);
    g_Wih1h[i] = __float2half(W2[i]);
    g_Whh1h[i] = __float2half(W3[i]);
}

// ======================= persistent recurrent kernel =========================
// Jobs: 2048 = 1024 units x 2 batch-groups of 8 (R11 mapping).
// Within a job: 4 gates x 4 batch-pairs packed u64 accumulators, FFMA2 inner.
template<int LAYER>
__device__ __forceinline__ void lstm_pass(
    int t, int gw, int lane,
    const int* __restrict__ ys, const float* __restrict__ embed,
    const __half* __restrict__ Wih, const __half* __restrict__ Whh,
    const float* __restrict__ bi,
    const float* __restrict__ ctx,
    const float* __restrict__ hprev,
    const float* __restrict__ h0new,
    float* __restrict__ cbuf, float* __restrict__ hout)
{
    for (int j = gw; j < 2048; j += NWARP) {
        const int u = j >> 1;
        const int b0 = (j & 1) << 3;
        int tok[8];
        if (LAYER == 0) {
            #pragma unroll
            for (int b = 0; b < 8; ++b)
                tok[b] = (t == 0) ? 1 : ys[(b0 + b) * LL + (t - 1)];
        }
        u64 acc[16];   // acc[g*4+bp] = packed (b0+2bp, b0+2bp+1)
        #pragma unroll
        for (int i = 0; i < 16; ++i) acc[i] = 0ull;

        // ---- segment 0: W_ih ----
        #pragma unroll
        for (int c = 0; c < 8; ++c) {
            const int k0 = c * 128 + lane * 4;
            u64 wd[4][4];
            #pragma unroll
            for (int g = 0; g < 4; ++g) {
                float4 w = ldw_h(Wih + (size_t)(u + g * HD) * 1024 + k0);
                wd[g][0] = pack2(w.x, w.x); wd[g][1] = pack2(w.y, w.y);
                wd[g][2] = pack2(w.z, w.z); wd[g][3] = pack2(w.w, w.w);
            }
            #pragma unroll
            for (int bp = 0; bp < 4; ++bp) {
                const float *pa, *pb;
                if (LAYER == 0) {
                    if (c < 4) {
                        pa = embed + (size_t)tok[2 * bp] * ED + k0;
                        pb = embed + (size_t)tok[2 * bp + 1] * ED + k0;
                    } else {
                        pa = ctx + (b0 + 2 * bp) * ENCD + (k0 - 512);
                        pb = ctx + (b0 + 2 * bp + 1) * ENCD + (k0 - 512);
                    }
                } else {
                    pa = h0new + (b0 + 2 * bp) * HD + k0;
                    pb = h0new + (b0 + 2 * bp + 1) * HD + k0;
                }
                float4 xa = *(const float4*)pa;
                float4 xb = *(const float4*)pb;
                u64 x0 = pack2(xa.x, xb.x), x1 = pack2(xa.y, xb.y);
                u64 x2 = pack2(xa.z, xb.z), x3 = pack2(xa.w, xb.w);
                #pragma unroll
                for (int g = 0; g < 4; ++g) {
                    fma2(acc[g * 4 + bp], x0, wd[g][0]);
                    fma2(acc[g * 4 + bp], x1, wd[g][1]);
                    fma2(acc[g * 4 + bp], x2, wd[g][2]);
                    fma2(acc[g * 4 + bp], x3, wd[g][3]);
                }
            }
        }
        // ---- segment 1: W_hh ----
        #pragma unroll
        for (int c = 0; c < 8; ++c) {
            const int k0 = c * 128 + lane * 4;
            u64 wd[4][4];
            #pragma unroll
            for (int g = 0; g < 4; ++g) {
                float4 w = ldw_h(Whh + (size_t)(u + g * HD) * 1024 + k0);
                wd[g][0] = pack2(w.x, w.x); wd[g][1] = pack2(w.y, w.y);
                wd[g][2] = pack2(w.z, w.z); wd[g][3] = pack2(w.w, w.w);
            }
            #pragma unroll
            for (int bp = 0; bp < 4; ++bp) {
                float4 xa = *(const float4*)(hprev + (b0 + 2 * bp) * HD + k0);
                float4 xb = *(const float4*)(hprev + (b0 + 2 * bp + 1) * HD + k0);
                u64 x0 = pack2(xa.x, xb.x), x1 = pack2(xa.y, xb.y);
                u64 x2 = pack2(xa.z, xb.z), x3 = pack2(xa.w, xb.w);
                #pragma unroll
                for (int g = 0; g < 4; ++g) {
                    fma2(acc[g * 4 + bp], x0, wd[g][0]);
                    fma2(acc[g * 4 + bp], x1, wd[g][1]);
                    fma2(acc[g * 4 + bp], x2, wd[g][2]);
                    fma2(acc[g * 4 + bp], x3, wd[g][3]);
                }
            }
        }

        // reduce 16 packed elems across 32 lanes:
        RSTAGE2(16, 8) RSTAGE2(8, 4) RSTAGE2(4, 2) RSTAGE2(2, 1)
        acc[0] = add2(acc[0], __shfl_xor_sync(0xffffffffu, acc[0], 1));
        // now lane l (and l^1) hold packed total for elem idx = (l>>1) & 15
        const u64 v = acc[0];
        const int bp = (lane & 7) >> 1;
        u64 pi = __shfl_sync(0xffffffffu, v, bp * 2);
        u64 pf = __shfl_sync(0xffffffffu, v, (4 + bp) * 2);
        u64 pg = __shfl_sync(0xffffffffu, v, (8 + bp) * 2);
        u64 po = __shfl_sync(0xffffffffu, v, (12 + bp) * 2);
        if (lane < 8) {
            const int b = b0 + lane;
            float ilo, ihi, flo, fhi, glo, ghi, olo, ohi;
            unpack2(pi, ilo, ihi); unpack2(pf, flo, fhi);
            unpack2(pg, glo, ghi); unpack2(po, olo, ohi);
            const int sel = lane & 1;
            float si_ = (sel ? ihi : ilo) + bi[u];
            float sf_ = (sel ? fhi : flo) + bi[u + HD];
            float sg_ = (sel ? ghi : glo) + bi[u + 2 * HD];
            float so_ = (sel ? ohi : olo) + bi[u + 3 * HD];
            const int idx = b * HD + u;
            float c = sigf(sf_) * cbuf[idx] + sigf(si_) * tanhf_fast(sg_);
            cbuf[idx] = c;
            float h = sigf(so_) * tanhf_fast(c);
            hout[idx] = h;
            if (LAYER == 1)
                g_dcat[((size_t)t * BB + b) * 1536 + u] = h + h0new[idx];
        }
    }
}

__global__ __launch_bounds__(NTHR, 1) void dec_persistent(
    const float* __restrict__ enc_out, const int* __restrict__ enc_lens,
    const int* __restrict__ ys, const float* __restrict__ embed,
    const float* __restrict__ bi0, const float* __restrict__ bi1,
    const float* __restrict__ Wdec, const float* __restrict__ vatt)
{
    const int lane = threadIdx.x & 31;
    const int gw = blockIdx.x * (NTHR / 32) + (threadIdx.x >> 5);
    const int gt = blockIdx.x * NTHR + threadIdx.x;
    unsigned mygen = 0;

    for (int t = 0; t < NSTEP; ++t) {
        const int par = t & 1;
        const float* h0r = g_h0[par];
        float* h0w = g_h0[par ^ 1];
        const float* h1r = g_h1[par];
        float* h1w = g_h1[par ^ 1];
        const float* ctxr = g_ctx[par];
        float* ctxw = g_ctx[par ^ 1];

        lstm_pass<0>(t, gw, lane, ys, embed, g_Wih0h, g_Whh0h, bi0, ctxr, h0r, h0w, g_c0, h0w);
        if (gt < BB * AD) g_dproj[gt] = 0.f;
        grid_sync(mygen);

        lstm_pass<1>(t, gw, lane, ys, embed, g_Wih1h, g_Whh1h, bi1, ctxr, h1r, h0w, g_c1, h1w);
        if (gt < BB * ENCD) {
            ctxw[gt] = 0.f;
            g_dcat[((size_t)t * BB + (gt >> 9)) * 1536 + 1024 + (gt & 511)] = 0.f;
        }
        if (gt < BB) g_awsum[gt] = 0.f;
        grid_sync(mygen);

        for (int job = gw; job < 2048; job += NWARP) {
            const int b = job >> 7;
            const int cg = (job >> 3) & 15;
            const int ks = job & 7;
            const int a0 = cg << 5;
            const float* dec = g_dcat + ((size_t)t * BB + b) * 1536 + ks * 128;
            const float* w = Wdec + (size_t)(ks * 128) * AD + a0 + lane;
            float s0 = 0.f, s1 = 0.f, s2 = 0.f, s3 = 0.f;
            #pragma unroll 8
            for (int k = 0; k < 128; k += 4) {
                s0 = fmaf(dec[k], w[(size_t)k * AD], s0);
                s1 = fmaf(dec[k + 1], w[(size_t)(k + 1) * AD], s1);
                s2 = fmaf(dec[k + 2], w[(size_t)(k + 2) * AD], s2);
                s3 = fmaf(dec[k + 3], w[(size_t)(k + 3) * AD], s3);
            }
            atomicAdd(&g_dproj[b * AD + a0 + lane], (s0 + s1) + (s2 + s3));
        }
        grid_sync(mygen);

        for (int job = gw; job < BB * TT; job += NWARP) {
            const int b = job >> 9, tt = job & (TT - 1);
            const float4* p4 = (const float4*)(g_encproj + (size_t)(b * TT + tt) * AD);
            const float4* d4 = (const float4*)(g_dproj + b * AD);
            const float4* v4 = (const float4*)vatt;
            float s = 0.f;
            #pragma unroll
            for (int i = lane; i < AD / 4; i += 32) {
                float4 p = __ldcs(p4 + i); float4 d = d4[i]; float4 vv = v4[i];
                s = fmaf(vv.x, tanh_apx(p.x + d.x), s);
                s = fmaf(vv.y, tanh_apx(p.y + d.y), s);
                s = fmaf(vv.z, tanh_apx(p.z + d.z), s);
                s = fmaf(vv.w, tanh_apx(p.w + d.w), s);
            }
            #pragma unroll
            for (int off = 16; off > 0; off >>= 1) s += __shfl_xor_sync(0xffffffffu, s, off);
            if (lane == 0) {
                float w = (tt < enc_lens[b]) ? __expf(s) : 0.f;
                g_aw[b * TT + tt] = w;
                if (w != 0.f) atomicAdd(&g_awsum[b], w);
            }
        }
        grid_sync(mygen);

        for (int job = gw; job < 2048; job += NWARP) {
            const int b = job >> 7;
            const int cg = (job >> 3) & 15;
            const int ts = job & 7;
            const int col = (cg << 5) + lane;
            const float inv = __fdividef(1.f, g_awsum[b]);
            const float* ao = g_aw + b * TT + ts * 64;
            const float* eo = enc_out + (size_t)b * TT * ENCD + (size_t)(ts * 64) * ENCD + col;
            float s0 = 0.f, s1 = 0.f;
            #pragma unroll 8
            for (int tt = 0; tt < 64; tt += 2) {
                s0 = fmaf(ao[tt], __ldcs(eo + (size_t)tt * ENCD), s0);
                s1 = fmaf(ao[tt + 1], __ldcs(eo + (size_t)(tt + 1) * ENCD), s1);
            }
            float cv = (s0 + s1) * inv;
            atomicAdd(&ctxw[b * ENCD + col], cv);
            atomicAdd(&g_dcat[((size_t)t * BB + b) * 1536 + 1024 + col], cv);
        }
        grid_sync(mygen);
    }
}

// ---- tiled fp32 GEMM (FFMA2). mode 0: plain; mode 3: tanh + bf16 hi/lo split ----
#define GBM 128
#define GBN 64
#define GBK 16

__global__ __launch_bounds__(256) void gemm_kernel(
    const float* __restrict__ Am, const float* __restrict__ Bm,
    const float* __restrict__ bias, float* __restrict__ Cm,
    int M, int N, int K, int mode)
{
    __shared__ float As[GBK][GBM + 4];
    __shared__ float Bs[GBK][GBN];
    const int tid = threadIdx.x;
    const int tx = tid & 15, ty = tid >> 4;
    const int n0 = blockIdx.x * GBN;
    const int m0 = blockIdx.y * GBM;
    u64 acc2[8][2];
    #pragma unroll
    for (int r = 0; r < 8; r++) { acc2[r][0] = 0ull; acc2[r][1] = 0ull; }

    for (int k0 = 0; k0 < K; k0 += GBK) {
        #pragma unroll
        for (int i = tid; i < (GBM * GBK) / 4; i += 256) {
            int row = i >> 2, kq = (i & 3) << 2;
            float4 v = make_float4(0.f, 0.f, 0.f, 0.f);
            int gm = m0 + row;
            if (gm < M) v = *(const float4*)(Am + (size_t)gm * K + k0 + kq);
            As[kq][row] = v.x; As[kq + 1][row] = v.y; As[kq + 2][row] = v.z; As[kq + 3][row] = v.w;
        }
        {
            int row = tid >> 4, nq = (tid & 15) << 2;
            float4 v = make_float4(0.f, 0.f, 0.f, 0.f);
            if (n0 + nq < N) v = *(const float4*)(Bm + (size_t)(k0 + row) * N + n0 + nq);
            *(float4*)&Bs[row][nq] = v;
        }
        __syncthreads();
        #pragma unroll
        for (int k = 0; k < GBK; k++) {
            float4 bv = *(const float4*)&Bs[k][tx << 2];
            u64 b01 = pack2(bv.x, bv.y);
            u64 b23 = pack2(bv.z, bv.w);
            #pragma unroll
            for (int r = 0; r < 8; r++) {
                float a = As[k][(ty << 3) + r];
                u64 aa = pack2(a, a);
                fma2(acc2[r][0], aa, b01);
                fma2(acc2[r][1], aa, b23);
            }
        }
        __syncthreads();
    }
    #pragma unroll
    for (int r = 0; r < 8; r++) {
        int m = m0 + (ty << 3) + r;
        if (m >= M) continue;
        float av[4];
        unpack2(acc2[r][0], av[0], av[1]);
        unpack2(acc2[r][1], av[2], av[3]);
        #pragma unroll
        for (int c = 0; c < 4; c++) {
            int n = n0 + (tx << 2) + c;
            if (n >= N) continue;
            float v = av[c] + bias[n];
            if (mode == 3) {
                v = tanhf_fast(v);
                __nv_bfloat16 h = __float2bfloat16(v);
                g_Ahi[(size_t)m * HD + n] = h;
                g_Alo[(size_t)m * HD + n] = __float2bfloat16(v - __bfloat162float(h));
            } else {
                Cm[(size_t)m * N + n] = v;
            }
        }
    }
}

// ---- W_out elementwise bf16 hi/lo split ----
__global__ void conv_wout_kernel(const float* __restrict__ W) {
    size_t i = (size_t)blockIdx.x * blockDim.x + threadIdx.x;
    if (i >= (size_t)HD * NPAD) return;
    int k = (int)(i / NPAD), n = (int)(i % NPAD);
    float v = (n < VD) ? W[(size_t)k * VD + n] : 0.f;
    __nv_bfloat16 h = __float2bfloat16(v);
    g_Bhi[i] = h;
    g_Blo[i] = __float2bfloat16(v - __bfloat162float(h));
}

// ======================= mma.sync bf16 split-precision logits GEMM =============
__device__ __forceinline__ uint32_t smem_u32(const void* p) {
    uint32_t a;
    asm("{ .reg .u64 t; cvta.to.shared.u64 t, %1; cvt.u32.u64 %0, t; }" : "=r"(a) : "l"(p));
    return a;
}
__device__ __forceinline__ void ldmA4(uint32_t* r, uint32_t addr) {
    asm volatile("ldmatrix.sync.aligned.m8n8.x4.shared.b16 {%0,%1,%2,%3}, [%4];"
                 : "=r"(r[0]), "=r"(r[1]), "=r"(r[2]), "=r"(r[3]) : "r"(addr));
}
__device__ __forceinline__ void ldmBT2(uint32_t* r, uint32_t addr) {
    asm volatile("ldmatrix.sync.aligned.m8n8.x2.trans.shared.b16 {%0,%1}, [%2];"
                 : "=r"(r[0]), "=r"(r[1]) : "r"(addr));
}
__device__ __forceinline__ void mma16816(float* d, const uint32_t* a, const uint32_t* b) {
    asm volatile(
        "mma.sync.aligned.m16n8k16.row.col.f32.bf16.bf16.f32 "
        "{%0,%1,%2,%3}, {%4,%5,%6,%7}, {%8,%9}, {%0,%1,%2,%3};"
        : "+f"(d[0]), "+f"(d[1]), "+f"(d[2]), "+f"(d[3])
        : "r"(a[0]), "r"(a[1]), "r"(a[2]), "r"(a[3]), "r"(b[0]), "r"(b[1]));
}

#define ASTR 40
#define BSTR 72

__global__ __launch_bounds__(256) void wout_mma_kernel(const float* __restrict__ bias,
                                                       float* __restrict__ out)
{
    __shared__ __nv_bfloat16 sAh[128 * ASTR], sAl[128 * ASTR];
    __shared__ __nv_bfloat16 sBh[32 * BSTR], sBl[32 * BSTR];
    const int tid = threadIdx.x;
    const int lane = tid & 31;
    const int w = tid >> 5;
    const int mwarp = w & 3, nwarp = w >> 2;
    const int n0 = blockIdx.x * 64;
    const int m0 = blockIdx.y * 128;

    const uint32_t sAh_b = smem_u32(sAh), sAl_b = smem_u32(sAl);
    const uint32_t sBh_b = smem_u32(sBh), sBl_b = smem_u32(sBl);
    const uint32_t aoff = ((mwarp * 32 + (lane & 15)) * ASTR + (lane >> 4) * 8) * 2;
    const uint32_t boff = ((lane & 15) * BSTR + nwarp * 32) * 2;

    float d[2][4][4];
    #pragma unroll
    for (int mt = 0; mt < 2; ++mt)
        #pragma unroll
        for (int nt = 0; nt < 4; ++nt)
            #pragma unroll
            for (int i = 0; i < 4; ++i) d[mt][nt][i] = 0.f;

    for (int kc = 0; kc < 32; ++kc) {
        const int kb = kc * 32;
        #pragma unroll
        for (int i = tid; i < 512; i += 256) {
            const int row = i >> 2, kq = (i & 3) << 3;
            const size_t src = (size_t)(m0 + row) * HD + kb + kq;
            *(float4*)((char*)sAh + (row * ASTR + kq) * 2) = *(const float4*)(g_Ahi + src);
            *(float4*)((char*)sAl + (row * ASTR + kq) * 2) = *(const float4*)(g_Alo + src);
        }
        {
            const int row = tid >> 3, nq = (tid & 7) << 3;
            const size_t src = (size_t)(kb + row) * NPAD + n0 + nq;
            *(float4*)((char*)sBh + (row * BSTR + nq) * 2) = *(const float4*)(g_Bhi + src);
            *(float4*)((char*)sBl + (row * BSTR + nq) * 2) = *(const float4*)(g_Blo + src);
        }
        __syncthreads();

        #pragma unroll
        for (int ks = 0; ks < 2; ++ks) {
            uint32_t ah[2][4], al[2][4], bh[4][2], bl[4][2];
            #pragma unroll
            for (int mt = 0; mt < 2; ++mt) {
                const uint32_t o = aoff + (mt * 16 * ASTR + ks * 16) * 2;
                ldmA4(ah[mt], sAh_b + o);
                ldmA4(al[mt], sAl_b + o);
            }
            #pragma unroll
            for (int nt = 0; nt < 4; ++nt) {
                const uint32_t o = boff + (ks * 16 * BSTR + nt * 8) * 2;
                ldmBT2(bh[nt], sBh_b + o);
                ldmBT2(bl[nt], sBl_b + o);
            }
            #pragma unroll
            for (int mt = 0; mt < 2; ++mt)
                #pragma unroll
                for (int nt = 0; nt < 4; ++nt) {
                    mma16816(d[mt][nt], ah[mt], bh[nt]);
                    mma16816(d[mt][nt], ah[mt], bl[nt]);
                    mma16816(d[mt][nt], al[mt], bh[nt]);
                }
        }
        __syncthreads();
    }

    const int grp = lane >> 2, tig = lane & 3;
    #pragma unroll
    for (int mt = 0; mt < 2; ++mt) {
        #pragma unroll
        for (int rr = 0; rr < 2; ++rr) {
            const int m = m0 + mwarp * 32 + mt * 16 + grp + rr * 8;
            if (m >= NSTEP * BB) continue;
            const int bb = m & 15, tt = m >> 4;
            float* orow = out + ((size_t)bb * NSTEP + tt) * VD;
            #pragma unroll
            for (int nt = 0; nt < 4; ++nt) {
                const int n = n0 + nwarp * 32 + nt * 8 + tig * 2;
                if (n < VD) {
                    orow[n] = d[mt][nt][rr * 2 + 0] + bias[n];
                    orow[n + 1] = d[mt][nt][rr * 2 + 1] + bias[n + 1];
                }
            }
        }
    }
}

extern "C" void kernel_launch(void* const* d_in, const int* in_sizes, int n_in,
                              void* d_out, int out_size)
{
    const float* enc_out  = (const float*)d_in[0];
    const int*   enc_lens = (const int*)d_in[1];
    const int*   ys       = (const int*)d_in[2];
    const float* embed    = (const float*)d_in[3];
    const float* Wih0     = (const float*)d_in[4];
    const float* Whh0     = (const float*)d_in[5];
    const float* b0       = (const float*)d_in[6];
    const float* Wih1     = (const float*)d_in[7];
    const float* Whh1     = (const float*)d_in[8];
    const float* b1       = (const float*)d_in[9];
    const float* W_enc    = (const float*)d_in[10];
    const float* b_att    = (const float*)d_in[11];
    const float* v_att    = (const float*)d_in[12];
    const float* W_dec    = (const float*)d_in[13];
    const float* W_bn     = (const float*)d_in[14];
    const float* b_bn     = (const float*)d_in[15];
    const float* W_out    = (const float*)d_in[16];
    const float* b_out    = (const float*)d_in[17];
    float* out = (float*)d_out;

    float *p_encproj, *p_dcat;
    cudaGetSymbolAddress((void**)&p_encproj, g_encproj);
    cudaGetSymbolAddress((void**)&p_dcat, g_dcat);

    init_kernel<<<(BB * HD + 255) / 256, 256>>>();

    conv_w_kernel<<<(unsigned)((WSZ + 255) / 256), 256>>>(Wih0, Whh0, Wih1, Whh1);

    {
        size_t tot = (size_t)HD * NPAD;
        conv_wout_kernel<<<(unsigned)((tot + 255) / 256), 256>>>(W_out);
    }

    {
        dim3 grid(AD / GBN, (BB * TT + GBM - 1) / GBM);
        gemm_kernel<<<grid, 256>>>(enc_out, W_enc, b_att, p_encproj, BB * TT, AD, ENCD, 0);
    }

    dec_persistent<<<NBLK, NTHR>>>(enc_out, enc_lens, ys, embed, b0, b1, W_dec, v_att);

    {
        dim3 grid(HD / GBN, (NSTEP * BB + GBM - 1) / GBM);
        gemm_kernel<<<grid, 256>>>(p_dcat, W_bn, b_bn, p_dcat /*unused*/, NSTEP * BB, HD, 1536, 3);
    }

    {
        dim3 grid(NPAD / 64, MROWS / 128);
        wout_mma_kernel<<<grid, 256>>>(b_out, out);
    }
    (void)in_sizes; (void)n_in; (void)out_size;
}

// round 14
// speedup vs baseline: 2.0913x; 1.0772x over previous
#include <cuda_runtime.h>
#include <cuda_bf16.h>
#include <cuda_fp16.h>
#include <cstdint>

#define BB 16
#define TT 512
#define LL 128
#define NSTEP 129
#define ENCD 512
#define HD 1024
#define ED 512
#define VD 10000
#define AD 512

#define NBLK 148
#define NTHR 512
#define NWARP (NBLK * (NTHR / 32))

typedef unsigned long long u64;

// ---- scratch (device globals; allocs are forbidden) ----
__device__ float g_encproj[(size_t)BB * TT * AD];
__device__ float g_h0[2][BB * HD];
__device__ float g_h1[2][BB * HD];
__device__ float g_c0[BB * HD];
__device__ float g_c1[BB * HD];
__device__ float g_ctx[2][BB * ENCD];
__device__ float g_dproj[BB * AD];
__device__ float g_aw[BB * TT];
__device__ float g_awsum[BB];
__device__ float g_dcat[(size_t)NSTEP * BB * 1536];
__device__ unsigned g_bar;
__device__ volatile unsigned g_gen;

// fp16 LSTM weights (L2-resident working set)
#define WSZ ((size_t)4096 * 1024)
__device__ __half g_Wih0h[WSZ];
__device__ __half g_Whh0h[WSZ];
__device__ __half g_Wih1h[WSZ];
__device__ __half g_Whh1h[WSZ];

// bf16 split buffers for tensor-core logits GEMM
#define MROWS 2176
#define NPAD 10048
__device__ __nv_bfloat16 g_Ahi[(size_t)MROWS * HD];
__device__ __nv_bfloat16 g_Alo[(size_t)MROWS * HD];
__device__ __nv_bfloat16 g_Bhi[(size_t)HD * NPAD];
__device__ __nv_bfloat16 g_Blo[(size_t)HD * NPAD];

__device__ __forceinline__ float sigf(float x) { return __fdividef(1.f, 1.f + __expf(-x)); }
__device__ __forceinline__ float tanhf_fast(float x) {
    float z = __expf(2.f * x);
    return 1.f - __fdividef(2.f, z + 1.f);
}
__device__ __forceinline__ float tanh_apx(float x) {
    float r; asm("tanh.approx.f32 %0, %1;" : "=f"(r) : "f"(x)); return r;
}

// packed f32x2 helpers (GEMM only)
__device__ __forceinline__ void fma2(u64& acc, u64 a, u64 b) {
    asm("fma.rn.f32x2 %0, %1, %2, %0;" : "+l"(acc) : "l"(a), "l"(b));
}
__device__ __forceinline__ u64 pack2(float lo, float hi) {
    u64 r; asm("mov.b64 %0, {%1, %2};" : "=l"(r) : "f"(lo), "f"(hi)); return r;
}
__device__ __forceinline__ void unpack2(u64 v, float& lo, float& hi) {
    asm("mov.b64 {%0, %1}, %2;" : "=f"(lo), "=f"(hi) : "l"(v));
}

// fp16x4 weight load via L2 (.cg), convert to float4
__device__ __forceinline__ float4 ldw_h(const __half* p) {
    uint2 v = __ldcg((const uint2*)p);
    float2 f0 = __half22float2(*(__half2*)&v.x);
    float2 f1 = __half22float2(*(__half2*)&v.y);
    return make_float4(f0.x, f0.y, f1.x, f1.y);
}

// R5-proven barrier
__device__ __forceinline__ void grid_sync(unsigned& mygen) {
    __syncthreads();
    if (threadIdx.x == 0) {
        unsigned tgt = mygen + 1u;
        __threadfence();
        if (atomicAdd(&g_bar, 1u) == NBLK - 1) {
            g_bar = 0u;
            __threadfence();
            g_gen = tgt;
        } else {
            while (g_gen < tgt) { __nanosleep(64); }
            __threadfence();
        }
    }
    mygen += 1u;
    __syncthreads();
}

#define DOT4(S, X, W) \
    S = fmaf((X).x, (W).x, S); S = fmaf((X).y, (W).y, S); \
    S = fmaf((X).z, (W).z, S); S = fmaf((X).w, (W).w, S);

#define RSTAGE(OFF, HALF) \
    { bool hi = (lane & OFF) != 0; \
      _Pragma("unroll") \
      for (int i = 0; i < HALF; ++i) { \
          float o0 = __shfl_xor_sync(0xffffffffu, acc[i], OFF); \
          float o1 = __shfl_xor_sync(0xffffffffu, acc[i + HALF], OFF); \
          acc[i] = hi ? (acc[i + HALF] + o1) : (acc[i] + o0); \
      } }

__global__ void init_kernel() {
    int i = blockIdx.x * blockDim.x + threadIdx.x;
    if (i < BB * HD) { g_h0[0][i] = 0.f; g_c0[i] = 0.f; g_h1[0][i] = 0.f; g_c1[i] = 0.f; }
    if (i < BB * ENCD) g_ctx[0][i] = 0.f;
    if (i == 0) { g_bar = 0u; g_gen = 0u; }
    for (size_t j = i; j < (size_t)(MROWS - 2064) * HD; j += (size_t)16384) {
        g_Ahi[(size_t)2064 * HD + j] = __float2bfloat16(0.f);
        g_Alo[(size_t)2064 * HD + j] = __float2bfloat16(0.f);
    }
}

// merged converters (single launch, keeps ncu capture slot on wout_mma)
__global__ void conv_all_kernel(const float* __restrict__ W0, const float* __restrict__ W1,
                                const float* __restrict__ W2, const float* __restrict__ W3,
                                const float* __restrict__ Wout) {
    size_t i = (size_t)blockIdx.x * blockDim.x + threadIdx.x;
    if (i < WSZ) {
        g_Wih0h[i] = __float2half(W0[i]);
        g_Whh0h[i] = __float2half(W1[i]);
        g_Wih1h[i] = __float2half(W2[i]);
        g_Whh1h[i] = __float2half(W3[i]);
    }
    if (i < (size_t)HD * NPAD) {
        int k = (int)(i / NPAD), n = (int)(i % NPAD);
        float v = (n < VD) ? Wout[(size_t)k * VD + n] : 0.f;
        __nv_bfloat16 h = __float2bfloat16(v);
        g_Bhi[i] = h;
        g_Blo[i] = __float2bfloat16(v - __bfloat162float(h));
    }
}

// ======================= persistent recurrent kernel (R11-proven) =============
template<int LAYER>
__device__ __forceinline__ void lstm_pass(
    int t, int gw, int lane,
    const int* __restrict__ ys, const float* __restrict__ embed,
    const __half* __restrict__ Wih, const __half* __restrict__ Whh,
    const float* __restrict__ bi,
    const float* __restrict__ ctx,
    const float* __restrict__ hprev,
    const float* __restrict__ h0new,
    float* __restrict__ cbuf, float* __restrict__ hout)
{
    for (int j = gw; j < 2048; j += NWARP) {
        const int u = j >> 1;
        const int b0 = (j & 1) << 3;
        int tok[8];
        if (LAYER == 0) {
            #pragma unroll
            for (int b = 0; b < 8; ++b)
                tok[b] = (t == 0) ? 1 : ys[(b0 + b) * LL + (t - 1)];
        }
        float acc[32];
        #pragma unroll
        for (int i = 0; i < 32; ++i) acc[i] = 0.f;

        #pragma unroll
        for (int c = 0; c < 8; ++c) {
            const int k0 = c * 128 + lane * 4;
            float4 xr[8];
            #pragma unroll
            for (int b = 0; b < 8; ++b) {
                const float* px;
                if (LAYER == 0)
                    px = (c < 4) ? (embed + (size_t)tok[b] * ED + k0)
                                 : (ctx + (b0 + b) * ENCD + (k0 - 512));
                else
                    px = h0new + (b0 + b) * HD + k0;
                xr[b] = *(const float4*)px;
            }
            #pragma unroll
            for (int g = 0; g < 4; ++g) {
                float4 w = ldw_h(Wih + (size_t)(u + g * HD) * 1024 + k0);
                #pragma unroll
                for (int b = 0; b < 8; ++b) { DOT4(acc[g * 8 + b], xr[b], w); }
            }
        }
        #pragma unroll
        for (int c = 0; c < 8; ++c) {
            const int k0 = c * 128 + lane * 4;
            float4 xr[8];
            #pragma unroll
            for (int b = 0; b < 8; ++b)
                xr[b] = *(const float4*)(hprev + (b0 + b) * HD + k0);
            #pragma unroll
            for (int g = 0; g < 4; ++g) {
                float4 w = ldw_h(Whh + (size_t)(u + g * HD) * 1024 + k0);
                #pragma unroll
                for (int b = 0; b < 8; ++b) { DOT4(acc[g * 8 + b], xr[b], w); }
            }
        }

        RSTAGE(16, 16) RSTAGE(8, 8) RSTAGE(4, 4) RSTAGE(2, 2) RSTAGE(1, 1)
        float v = acc[0];
        float sf = __shfl_sync(0xffffffffu, v, (lane & 7) + 8);
        float sg = __shfl_sync(0xffffffffu, v, (lane & 7) + 16);
        float so = __shfl_sync(0xffffffffu, v, (lane & 7) + 24);
        if (lane < 8) {
            const int b = b0 + lane;
            const int idx = b * HD + u;
            float si_ = v + bi[u];
            float sf_ = sf + bi[u + HD];
            float sg_ = sg + bi[u + 2 * HD];
            float so_ = so + bi[u + 3 * HD];
            float c = sigf(sf_) * cbuf[idx] + sigf(si_) * tanhf_fast(sg_);
            cbuf[idx] = c;
            float h = sigf(so_) * tanhf_fast(c);
            hout[idx] = h;
            if (LAYER == 1)
                g_dcat[((size_t)t * BB + b) * 1536 + u] = h + h0new[idx];
        }
    }
}

__global__ __launch_bounds__(NTHR, 1) void dec_persistent(
    const float* __restrict__ enc_out, const int* __restrict__ enc_lens,
    const int* __restrict__ ys, const float* __restrict__ embed,
    const float* __restrict__ bi0, const float* __restrict__ bi1,
    const float* __restrict__ Wdec, const float* __restrict__ vatt)
{
    const int lane = threadIdx.x & 31;
    const int gw = blockIdx.x * (NTHR / 32) + (threadIdx.x >> 5);
    const int gt = blockIdx.x * NTHR + threadIdx.x;
    unsigned mygen = 0;

    for (int t = 0; t < NSTEP; ++t) {
        const int par = t & 1;
        const float* h0r = g_h0[par];
        float* h0w = g_h0[par ^ 1];
        const float* h1r = g_h1[par];
        float* h1w = g_h1[par ^ 1];
        const float* ctxr = g_ctx[par];
        float* ctxw = g_ctx[par ^ 1];

        lstm_pass<0>(t, gw, lane, ys, embed, g_Wih0h, g_Whh0h, bi0, ctxr, h0r, h0w, g_c0, h0w);
        if (gt < BB * AD) g_dproj[gt] = 0.f;
        grid_sync(mygen);

        lstm_pass<1>(t, gw, lane, ys, embed, g_Wih1h, g_Whh1h, bi1, ctxr, h1r, h0w, g_c1, h1w);
        if (gt < BB * ENCD) {
            ctxw[gt] = 0.f;
            g_dcat[((size_t)t * BB + (gt >> 9)) * 1536 + 1024 + (gt & 511)] = 0.f;
        }
        if (gt < BB) g_awsum[gt] = 0.f;
        grid_sync(mygen);

        for (int job = gw; job < 2048; job += NWARP) {
            const int b = job >> 7;
            const int cg = (job >> 3) & 15;
            const int ks = job & 7;
            const int a0 = cg << 5;
            const float* dec = g_dcat + ((size_t)t * BB + b) * 1536 + ks * 128;
            const float* w = Wdec + (size_t)(ks * 128) * AD + a0 + lane;
            float s0 = 0.f, s1 = 0.f, s2 = 0.f, s3 = 0.f;
            #pragma unroll 8
            for (int k = 0; k < 128; k += 4) {
                s0 = fmaf(dec[k], w[(size_t)k * AD], s0);
                s1 = fmaf(dec[k + 1], w[(size_t)(k + 1) * AD], s1);
                s2 = fmaf(dec[k + 2], w[(size_t)(k + 2) * AD], s2);
                s3 = fmaf(dec[k + 3], w[(size_t)(k + 3) * AD], s3);
            }
            atomicAdd(&g_dproj[b * AD + a0 + lane], (s0 + s1) + (s2 + s3));
        }
        grid_sync(mygen);

        for (int job = gw; job < BB * TT; job += NWARP) {
            const int b = job >> 9, tt = job & (TT - 1);
            const float4* p4 = (const float4*)(g_encproj + (size_t)(b * TT + tt) * AD);
            const float4* d4 = (const float4*)(g_dproj + b * AD);
            const float4* v4 = (const float4*)vatt;
            float s = 0.f;
            #pragma unroll
            for (int i = lane; i < AD / 4; i += 32) {
                float4 p = __ldcs(p4 + i); float4 d = d4[i]; float4 vv = v4[i];
                s = fmaf(vv.x, tanh_apx(p.x + d.x), s);
                s = fmaf(vv.y, tanh_apx(p.y + d.y), s);
                s = fmaf(vv.z, tanh_apx(p.z + d.z), s);
                s = fmaf(vv.w, tanh_apx(p.w + d.w), s);
            }
            #pragma unroll
            for (int off = 16; off > 0; off >>= 1) s += __shfl_xor_sync(0xffffffffu, s, off);
            if (lane == 0) {
                float w = (tt < enc_lens[b]) ? __expf(s) : 0.f;
                g_aw[b * TT + tt] = w;
                if (w != 0.f) atomicAdd(&g_awsum[b], w);
            }
        }
        grid_sync(mygen);

        for (int job = gw; job < 2048; job += NWARP) {
            const int b = job >> 7;
            const int cg = (job >> 3) & 15;
            const int ts = job & 7;
            const int col = (cg << 5) + lane;
            const float inv = __fdividef(1.f, g_awsum[b]);
            const float* ao = g_aw + b * TT + ts * 64;
            const float* eo = enc_out + (size_t)b * TT * ENCD + (size_t)(ts * 64) * ENCD + col;
            float s0 = 0.f, s1 = 0.f;
            #pragma unroll 8
            for (int tt = 0; tt < 64; tt += 2) {
                s0 = fmaf(ao[tt], __ldcs(eo + (size_t)tt * ENCD), s0);
                s1 = fmaf(ao[tt + 1], __ldcs(eo + (size_t)(tt + 1) * ENCD), s1);
            }
            float cv = (s0 + s1) * inv;
            atomicAdd(&ctxw[b * ENCD + col], cv);
            atomicAdd(&g_dcat[((size_t)t * BB + b) * 1536 + 1024 + col], cv);
        }
        grid_sync(mygen);
    }
}

// ---- tiled fp32 GEMM (FFMA2). mode 0: plain; mode 3: tanh + bf16 hi/lo split ----
#define GBM 128
#define GBN 64
#define GBK 16

__global__ __launch_bounds__(256) void gemm_kernel(
    const float* __restrict__ Am, const float* __restrict__ Bm,
    const float* __restrict__ bias, float* __restrict__ Cm,
    int M, int N, int K, int mode)
{
    __shared__ float As[GBK][GBM + 4];
    __shared__ float Bs[GBK][GBN];
    const int tid = threadIdx.x;
    const int tx = tid & 15, ty = tid >> 4;
    const int n0 = blockIdx.x * GBN;
    const int m0 = blockIdx.y * GBM;
    u64 acc2[8][2];
    #pragma unroll
    for (int r = 0; r < 8; r++) { acc2[r][0] = 0ull; acc2[r][1] = 0ull; }

    for (int k0 = 0; k0 < K; k0 += GBK) {
        #pragma unroll
        for (int i = tid; i < (GBM * GBK) / 4; i += 256) {
            int row = i >> 2, kq = (i & 3) << 2;
            float4 v = make_float4(0.f, 0.f, 0.f, 0.f);
            int gm = m0 + row;
            if (gm < M) v = *(const float4*)(Am + (size_t)gm * K + k0 + kq);
            As[kq][row] = v.x; As[kq + 1][row] = v.y; As[kq + 2][row] = v.z; As[kq + 3][row] = v.w;
        }
        {
            int row = tid >> 4, nq = (tid & 15) << 2;
            float4 v = make_float4(0.f, 0.f, 0.f, 0.f);
            if (n0 + nq < N) v = *(const float4*)(Bm + (size_t)(k0 + row) * N + n0 + nq);
            *(float4*)&Bs[row][nq] = v;
        }
        __syncthreads();
        #pragma unroll
        for (int k = 0; k < GBK; k++) {
            float4 bv = *(const float4*)&Bs[k][tx << 2];
            u64 b01 = pack2(bv.x, bv.y);
            u64 b23 = pack2(bv.z, bv.w);
            #pragma unroll
            for (int r = 0; r < 8; r++) {
                float a = As[k][(ty << 3) + r];
                u64 aa = pack2(a, a);
                fma2(acc2[r][0], aa, b01);
                fma2(acc2[r][1], aa, b23);
            }
        }
        __syncthreads();
    }
    #pragma unroll
    for (int r = 0; r < 8; r++) {
        int m = m0 + (ty << 3) + r;
        if (m >= M) continue;
        float av[4];
        unpack2(acc2[r][0], av[0], av[1]);
        unpack2(acc2[r][1], av[2], av[3]);
        #pragma unroll
        for (int c = 0; c < 4; c++) {
            int n = n0 + (tx << 2) + c;
            if (n >= N) continue;
            float v = av[c] + bias[n];
            if (mode == 3) {
                v = tanhf_fast(v);
                __nv_bfloat16 h = __float2bfloat16(v);
                g_Ahi[(size_t)m * HD + n] = h;
                g_Alo[(size_t)m * HD + n] = __float2bfloat16(v - __bfloat162float(h));
            } else {
                Cm[(size_t)m * N + n] = v;
            }
        }
    }
}

// ======================= pipelined mma.sync bf16 split logits GEMM =============
__device__ __forceinline__ uint32_t smem_u32(const void* p) {
    uint32_t a;
    asm("{ .reg .u64 t; cvta.to.shared.u64 t, %1; cvt.u32.u64 %0, t; }" : "=r"(a) : "l"(p));
    return a;
}
__device__ __forceinline__ void cpa16(uint32_t dst, const void* src) {
    asm volatile("cp.async.ca.shared.global [%0], [%1], 16;" :: "r"(dst), "l"(src));
}
#define CP_COMMIT() asm volatile("cp.async.commit_group;" ::: "memory")
#define CP_WAIT1() asm volatile("cp.async.wait_group 1;" ::: "memory")
#define CP_WAIT0() asm volatile("cp.async.wait_group 0;" ::: "memory")

__device__ __forceinline__ void ldmA4(uint32_t* r, uint32_t addr) {
    asm volatile("ldmatrix.sync.aligned.m8n8.x4.shared.b16 {%0,%1,%2,%3}, [%4];"
                 : "=r"(r[0]), "=r"(r[1]), "=r"(r[2]), "=r"(r[3]) : "r"(addr));
}
__device__ __forceinline__ void ldmBT2(uint32_t* r, uint32_t addr) {
    asm volatile("ldmatrix.sync.aligned.m8n8.x2.trans.shared.b16 {%0,%1}, [%2];"
                 : "=r"(r[0]), "=r"(r[1]) : "r"(addr));
}
__device__ __forceinline__ void mma16816(float* d, const uint32_t* a, const uint32_t* b) {
    asm volatile(
        "mma.sync.aligned.m16n8k16.row.col.f32.bf16.bf16.f32 "
        "{%0,%1,%2,%3}, {%4,%5,%6,%7}, {%8,%9}, {%0,%1,%2,%3};"
        : "+f"(d[0]), "+f"(d[1]), "+f"(d[2]), "+f"(d[3])
        : "r"(a[0]), "r"(a[1]), "r"(a[2]), "r"(a[3]), "r"(b[0]), "r"(b[1]));
}

#define ASTR2 24                       // 16 k + 8 pad (bf16 elems)
#define BSTR 72                        // 64 n + 8 pad
#define ASTAGE (128 * ASTR2 * 2)       // bytes per A buffer stage
#define BSTAGE (16 * BSTR * 2)         // bytes per B buffer stage
#define NKCH 64                        // K chunks of 16

__global__ __launch_bounds__(256) void wout_mma_kernel(const float* __restrict__ bias,
                                                       float* __restrict__ out)
{
    __shared__ __nv_bfloat16 sAh[2 * 128 * ASTR2], sAl[2 * 128 * ASTR2];
    __shared__ __nv_bfloat16 sBh[2 * 16 * BSTR], sBl[2 * 16 * BSTR];
    const int tid = threadIdx.x;
    const int lane = tid & 31;
    const int w = tid >> 5;
    const int mwarp = w & 3, nwarp = w >> 2;
    const int n0 = blockIdx.x * 64;
    const int m0 = blockIdx.y * 128;

    const uint32_t sAh_b = smem_u32(sAh), sAl_b = smem_u32(sAl);
    const uint32_t sBh_b = smem_u32(sBh), sBl_b = smem_u32(sBl);
    const uint32_t aoff = ((mwarp * 32 + (lane & 15)) * ASTR2 + (lane >> 4) * 8) * 2;
    const uint32_t boff = ((lane & 15) * BSTR + nwarp * 32) * 2;

    // per-thread cp.async assignments
    const int ar = tid >> 1, ac = tid & 1;                 // A: 256 chunks (row, 16B-col)
    const int bq = tid & 127, br = bq >> 3, bc = bq & 7;   // B: 128 chunks x2 halves

    float d[2][4][4];
    #pragma unroll
    for (int mt = 0; mt < 2; ++mt)
        #pragma unroll
        for (int nt = 0; nt < 4; ++nt)
            #pragma unroll
            for (int i = 0; i < 4; ++i) d[mt][nt][i] = 0.f;

    // stage loader
    auto load_stage = [&](int st, int kc) {
        const int kb = kc * 16;
        const uint32_t ad = (uint32_t)(st * ASTAGE) + (ar * ASTR2 + ac * 8) * 2;
        const size_t as = (size_t)(m0 + ar) * HD + kb + ac * 8;
        cpa16(sAh_b + ad, g_Ahi + as);
        cpa16(sAl_b + ad, g_Alo + as);
        const uint32_t bd = (uint32_t)(st * BSTAGE) + (br * BSTR + bc * 8) * 2;
        const size_t bs = (size_t)(kb + br) * NPAD + n0 + bc * 8;
        if (tid < 128) cpa16(sBh_b + bd, g_Bhi + bs);
        else           cpa16(sBl_b + bd, g_Blo + bs);
    };

    load_stage(0, 0);
    CP_COMMIT();

    for (int kc = 0; kc < NKCH; ++kc) {
        const int cur = kc & 1;
        if (kc + 1 < NKCH) { load_stage((kc + 1) & 1, kc + 1); CP_COMMIT(); CP_WAIT1(); }
        else { CP_WAIT0(); }
        __syncthreads();

        uint32_t ah[2][4], al[2][4], bh[4][2], bl[4][2];
        #pragma unroll
        for (int mt = 0; mt < 2; ++mt) {
            const uint32_t o = (uint32_t)(cur * ASTAGE) + aoff + (mt * 16 * ASTR2) * 2;
            ldmA4(ah[mt], sAh_b + o);
            ldmA4(al[mt], sAl_b + o);
        }
        #pragma unroll
        for (int nt = 0; nt < 4; ++nt) {
            const uint32_t o = (uint32_t)(cur * BSTAGE) + boff + (nt * 8) * 2;
            ldmBT2(bh[nt], sBh_b + o);
            ldmBT2(bl[nt], sBl_b + o);
        }
        #pragma unroll
        for (int mt = 0; mt < 2; ++mt)
            #pragma unroll
            for (int nt = 0; nt < 4; ++nt) {
                mma16816(d[mt][nt], ah[mt], bh[nt]);
                mma16816(d[mt][nt], ah[mt], bl[nt]);
                mma16816(d[mt][nt], al[mt], bh[nt]);
            }
        __syncthreads();
    }

    const int grp = lane >> 2, tig = lane & 3;
    #pragma unroll
    for (int mt = 0; mt < 2; ++mt) {
        #pragma unroll
        for (int rr = 0; rr < 2; ++rr) {
            const int m = m0 + mwarp * 32 + mt * 16 + grp + rr * 8;
            if (m >= NSTEP * BB) continue;
            const int bb = m & 15, tt = m >> 4;
            float* orow = out + ((size_t)bb * NSTEP + tt) * VD;
            #pragma unroll
            for (int nt = 0; nt < 4; ++nt) {
                const int n = n0 + nwarp * 32 + nt * 8 + tig * 2;
                if (n < VD) {
                    orow[n] = d[mt][nt][rr * 2 + 0] + bias[n];
                    orow[n + 1] = d[mt][nt][rr * 2 + 1] + bias[n + 1];
                }
            }
        }
    }
}

extern "C" void kernel_launch(void* const* d_in, const int* in_sizes, int n_in,
                              void* d_out, int out_size)
{
    const float* enc_out  = (const float*)d_in[0];
    const int*   enc_lens = (const int*)d_in[1];
    const int*   ys       = (const int*)d_in[2];
    const float* embed    = (const float*)d_in[3];
    const float* Wih0     = (const float*)d_in[4];
    const float* Whh0     = (const float*)d_in[5];
    const float* b0       = (const float*)d_in[6];
    const float* Wih1     = (const float*)d_in[7];
    const float* Whh1     = (const float*)d_in[8];
    const float* b1       = (const float*)d_in[9];
    const float* W_enc    = (const float*)d_in[10];
    const float* b_att    = (const float*)d_in[11];
    const float* v_att    = (const float*)d_in[12];
    const float* W_dec    = (const float*)d_in[13];
    const float* W_bn     = (const float*)d_in[14];
    const float* b_bn     = (const float*)d_in[15];
    const float* W_out    = (const float*)d_in[16];
    const float* b_out    = (const float*)d_in[17];
    float* out = (float*)d_out;

    float *p_encproj, *p_dcat;
    cudaGetSymbolAddress((void**)&p_encproj, g_encproj);
    cudaGetSymbolAddress((void**)&p_dcat, g_dcat);

    init_kernel<<<(BB * HD + 255) / 256, 256>>>();

    {
        size_t tot = (size_t)HD * NPAD;   // >= WSZ
        conv_all_kernel<<<(unsigned)((tot + 255) / 256), 256>>>(Wih0, Whh0, Wih1, Whh1, W_out);
    }

    {
        dim3 grid(AD / GBN, (BB * TT + GBM - 1) / GBM);
        gemm_kernel<<<grid, 256>>>(enc_out, W_enc, b_att, p_encproj, BB * TT, AD, ENCD, 0);
    }

    dec_persistent<<<NBLK, NTHR>>>(enc_out, enc_lens, ys, embed, b0, b1, W_dec, v_att);

    {
        dim3 grid(HD / GBN, (NSTEP * BB + GBM - 1) / GBM);
        gemm_kernel<<<grid, 256>>>(p_dcat, W_bn, b_bn, p_dcat /*unused*/, NSTEP * BB, HD, 1536, 3);
    }

    {
        dim3 grid(NPAD / 64, MROWS / 128);
        wout_mma_kernel<<<grid, 256>>>(b_out, out);
    }
    (void)in_sizes; (void)n_in; (void)out_size;
}

// round 15
// speedup vs baseline: 2.1831x; 1.0438x over previous
#include <cuda_runtime.h>
#include <cuda_bf16.h>
#include <cuda_fp16.h>
#include <cstdint>

#define BB 16
#define TT 512
#define LL 128
#define NSTEP 129
#define ENCD 512
#define HD 1024
#define ED 512
#define VD 10000
#define AD 512

#define NBLK 148
#define NTHR 512
#define NWARP (NBLK * (NTHR / 32))

typedef unsigned long long u64;

// ---- scratch (device globals; allocs are forbidden) ----
__device__ float g_encproj[(size_t)BB * TT * AD];
__device__ float g_h0[2][BB * HD];
__device__ float g_h1[2][BB * HD];
__device__ float g_c0[BB * HD];
__device__ float g_c1[BB * HD];
__device__ float g_ctx[2][BB * ENCD];
__device__ float g_dproj[BB * AD];
__device__ float g_aw[BB * TT];
__device__ float g_awsum[BB];
__device__ float g_dcat[(size_t)NSTEP * BB * 1536];
__device__ unsigned g_bar;
__device__ volatile unsigned g_gen;

// fp16 LSTM weights (L2-resident working set)
#define WSZ ((size_t)4096 * 1024)
__device__ __half g_Wih0h[WSZ];
__device__ __half g_Whh0h[WSZ];
__device__ __half g_Wih1h[WSZ];
__device__ __half g_Whh1h[WSZ];

// fp16 buffers for tensor-core logits GEMM (single precision pass)
#define MROWS 2176
#define NPAD 10048
__device__ __half g_Ah[(size_t)MROWS * HD];   // [m][k]
__device__ __half g_Bh[(size_t)HD * NPAD];    // [k][n]

__device__ __forceinline__ float sigf(float x) { return __fdividef(1.f, 1.f + __expf(-x)); }
__device__ __forceinline__ float tanhf_fast(float x) {
    float z = __expf(2.f * x);
    return 1.f - __fdividef(2.f, z + 1.f);
}
__device__ __forceinline__ float tanh_apx(float x) {
    float r; asm("tanh.approx.f32 %0, %1;" : "=f"(r) : "f"(x)); return r;
}

// packed f32x2 helpers (fp32 GEMM only)
__device__ __forceinline__ void fma2(u64& acc, u64 a, u64 b) {
    asm("fma.rn.f32x2 %0, %1, %2, %0;" : "+l"(acc) : "l"(a), "l"(b));
}
__device__ __forceinline__ u64 pack2(float lo, float hi) {
    u64 r; asm("mov.b64 %0, {%1, %2};" : "=l"(r) : "f"(lo), "f"(hi)); return r;
}
__device__ __forceinline__ void unpack2(u64 v, float& lo, float& hi) {
    asm("mov.b64 {%0, %1}, %2;" : "=f"(lo), "=f"(hi) : "l"(v));
}

// fp16x4 weight load via L2 (.cg), convert to float4
__device__ __forceinline__ float4 ldw_h(const __half* p) {
    uint2 v = __ldcg((const uint2*)p);
    float2 f0 = __half22float2(*(__half2*)&v.x);
    float2 f1 = __half22float2(*(__half2*)&v.y);
    return make_float4(f0.x, f0.y, f1.x, f1.y);
}

// R5-proven barrier
__device__ __forceinline__ void grid_sync(unsigned& mygen) {
    __syncthreads();
    if (threadIdx.x == 0) {
        unsigned tgt = mygen + 1u;
        __threadfence();
        if (atomicAdd(&g_bar, 1u) == NBLK - 1) {
            g_bar = 0u;
            __threadfence();
            g_gen = tgt;
        } else {
            while (g_gen < tgt) { __nanosleep(64); }
            __threadfence();
        }
    }
    mygen += 1u;
    __syncthreads();
}

#define DOT4(S, X, W) \
    S = fmaf((X).x, (W).x, S); S = fmaf((X).y, (W).y, S); \
    S = fmaf((X).z, (W).z, S); S = fmaf((X).w, (W).w, S);

#define RSTAGE(OFF, HALF) \
    { bool hi = (lane & OFF) != 0; \
      _Pragma("unroll") \
      for (int i = 0; i < HALF; ++i) { \
          float o0 = __shfl_xor_sync(0xffffffffu, acc[i], OFF); \
          float o1 = __shfl_xor_sync(0xffffffffu, acc[i + HALF], OFF); \
          acc[i] = hi ? (acc[i + HALF] + o1) : (acc[i] + o0); \
      } }

__global__ void init_kernel() {
    int i = blockIdx.x * blockDim.x + threadIdx.x;
    if (i < BB * HD) { g_h0[0][i] = 0.f; g_c0[i] = 0.f; g_h1[0][i] = 0.f; g_c1[i] = 0.f; }
    if (i < BB * ENCD) g_ctx[0][i] = 0.f;
    if (i == 0) { g_bar = 0u; g_gen = 0u; }
    for (size_t j = i; j < (size_t)(MROWS - 2064) * HD; j += (size_t)16384)
        g_Ah[(size_t)2064 * HD + j] = __float2half(0.f);
}

// merged converters
__global__ void conv_all_kernel(const float* __restrict__ W0, const float* __restrict__ W1,
                                const float* __restrict__ W2, const float* __restrict__ W3,
                                const float* __restrict__ Wout) {
    size_t i = (size_t)blockIdx.x * blockDim.x + threadIdx.x;
    if (i < WSZ) {
        g_Wih0h[i] = __float2half(W0[i]);
        g_Whh0h[i] = __float2half(W1[i]);
        g_Wih1h[i] = __float2half(W2[i]);
        g_Whh1h[i] = __float2half(W3[i]);
    }
    if (i < (size_t)HD * NPAD) {
        int n = (int)(i % NPAD);
        float v = (n < VD) ? Wout[(size_t)(i / NPAD) * VD + n] : 0.f;
        g_Bh[i] = __float2half(v);
    }
}

// ======================= persistent recurrent kernel (R11-proven) =============
template<int LAYER>
__device__ __forceinline__ void lstm_pass(
    int t, int gw, int lane,
    const int* __restrict__ ys, const float* __restrict__ embed,
    const __half* __restrict__ Wih, const __half* __restrict__ Whh,
    const float* __restrict__ bi,
    const float* __restrict__ ctx,
    const float* __restrict__ hprev,
    const float* __restrict__ h0new,
    float* __restrict__ cbuf, float* __restrict__ hout)
{
    for (int j = gw; j < 2048; j += NWARP) {
        const int u = j >> 1;
        const int b0 = (j & 1) << 3;
        int tok[8];
        if (LAYER == 0) {
            #pragma unroll
            for (int b = 0; b < 8; ++b)
                tok[b] = (t == 0) ? 1 : ys[(b0 + b) * LL + (t - 1)];
        }
        float acc[32];
        #pragma unroll
        for (int i = 0; i < 32; ++i) acc[i] = 0.f;

        #pragma unroll
        for (int c = 0; c < 8; ++c) {
            const int k0 = c * 128 + lane * 4;
            float4 xr[8];
            #pragma unroll
            for (int b = 0; b < 8; ++b) {
                const float* px;
                if (LAYER == 0)
                    px = (c < 4) ? (embed + (size_t)tok[b] * ED + k0)
                                 : (ctx + (b0 + b) * ENCD + (k0 - 512));
                else
                    px = h0new + (b0 + b) * HD + k0;
                xr[b] = *(const float4*)px;
            }
            #pragma unroll
            for (int g = 0; g < 4; ++g) {
                float4 w = ldw_h(Wih + (size_t)(u + g * HD) * 1024 + k0);
                #pragma unroll
                for (int b = 0; b < 8; ++b) { DOT4(acc[g * 8 + b], xr[b], w); }
            }
        }
        #pragma unroll
        for (int c = 0; c < 8; ++c) {
            const int k0 = c * 128 + lane * 4;
            float4 xr[8];
            #pragma unroll
            for (int b = 0; b < 8; ++b)
                xr[b] = *(const float4*)(hprev + (b0 + b) * HD + k0);
            #pragma unroll
            for (int g = 0; g < 4; ++g) {
                float4 w = ldw_h(Whh + (size_t)(u + g * HD) * 1024 + k0);
                #pragma unroll
                for (int b = 0; b < 8; ++b) { DOT4(acc[g * 8 + b], xr[b], w); }
            }
        }

        RSTAGE(16, 16) RSTAGE(8, 8) RSTAGE(4, 4) RSTAGE(2, 2) RSTAGE(1, 1)
        float v = acc[0];
        float sf = __shfl_sync(0xffffffffu, v, (lane & 7) + 8);
        float sg = __shfl_sync(0xffffffffu, v, (lane & 7) + 16);
        float so = __shfl_sync(0xffffffffu, v, (lane & 7) + 24);
        if (lane < 8) {
            const int b = b0 + lane;
            const int idx = b * HD + u;
            float si_ = v + bi[u];
            float sf_ = sf + bi[u + HD];
            float sg_ = sg + bi[u + 2 * HD];
            float so_ = so + bi[u + 3 * HD];
            float c = sigf(sf_) * cbuf[idx] + sigf(si_) * tanhf_fast(sg_);
            cbuf[idx] = c;
            float h = sigf(so_) * tanhf_fast(c);
            hout[idx] = h;
            if (LAYER == 1)
                g_dcat[((size_t)t * BB + b) * 1536 + u] = h + h0new[idx];
        }
    }
}

__global__ __launch_bounds__(NTHR, 1) void dec_persistent(
    const float* __restrict__ enc_out, const int* __restrict__ enc_lens,
    const int* __restrict__ ys, const float* __restrict__ embed,
    const float* __restrict__ bi0, const float* __restrict__ bi1,
    const float* __restrict__ Wdec, const float* __restrict__ vatt)
{
    const int lane = threadIdx.x & 31;
    const int gw = blockIdx.x * (NTHR / 32) + (threadIdx.x >> 5);
    const int gt = blockIdx.x * NTHR + threadIdx.x;
    unsigned mygen = 0;

    for (int t = 0; t < NSTEP; ++t) {
        const int par = t & 1;
        const float* h0r = g_h0[par];
        float* h0w = g_h0[par ^ 1];
        const float* h1r = g_h1[par];
        float* h1w = g_h1[par ^ 1];
        const float* ctxr = g_ctx[par];
        float* ctxw = g_ctx[par ^ 1];

        lstm_pass<0>(t, gw, lane, ys, embed, g_Wih0h, g_Whh0h, bi0, ctxr, h0r, h0w, g_c0, h0w);
        if (gt < BB * AD) g_dproj[gt] = 0.f;
        grid_sync(mygen);

        lstm_pass<1>(t, gw, lane, ys, embed, g_Wih1h, g_Whh1h, bi1, ctxr, h1r, h0w, g_c1, h1w);
        if (gt < BB * ENCD) {
            ctxw[gt] = 0.f;
            g_dcat[((size_t)t * BB + (gt >> 9)) * 1536 + 1024 + (gt & 511)] = 0.f;
        }
        if (gt < BB) g_awsum[gt] = 0.f;
        grid_sync(mygen);

        for (int job = gw; job < 2048; job += NWARP) {
            const int b = job >> 7;
            const int cg = (job >> 3) & 15;
            const int ks = job & 7;
            const int a0 = cg << 5;
            const float* dec = g_dcat + ((size_t)t * BB + b) * 1536 + ks * 128;
            const float* w = Wdec + (size_t)(ks * 128) * AD + a0 + lane;
            float s0 = 0.f, s1 = 0.f, s2 = 0.f, s3 = 0.f;
            #pragma unroll 8
            for (int k = 0; k < 128; k += 4) {
                s0 = fmaf(dec[k], w[(size_t)k * AD], s0);
                s1 = fmaf(dec[k + 1], w[(size_t)(k + 1) * AD], s1);
                s2 = fmaf(dec[k + 2], w[(size_t)(k + 2) * AD], s2);
                s3 = fmaf(dec[k + 3], w[(size_t)(k + 3) * AD], s3);
            }
            atomicAdd(&g_dproj[b * AD + a0 + lane], (s0 + s1) + (s2 + s3));
        }
        grid_sync(mygen);

        for (int job = gw; job < BB * TT; job += NWARP) {
            const int b = job >> 9, tt = job & (TT - 1);
            const float4* p4 = (const float4*)(g_encproj + (size_t)(b * TT + tt) * AD);
            const float4* d4 = (const float4*)(g_dproj + b * AD);
            const float4* v4 = (const float4*)vatt;
            float s = 0.f;
            #pragma unroll
            for (int i = lane; i < AD / 4; i += 32) {
                float4 p = __ldcs(p4 + i); float4 d = d4[i]; float4 vv = v4[i];
                s = fmaf(vv.x, tanh_apx(p.x + d.x), s);
                s = fmaf(vv.y, tanh_apx(p.y + d.y), s);
                s = fmaf(vv.z, tanh_apx(p.z + d.z), s);
                s = fmaf(vv.w, tanh_apx(p.w + d.w), s);
            }
            #pragma unroll
            for (int off = 16; off > 0; off >>= 1) s += __shfl_xor_sync(0xffffffffu, s, off);
            if (lane == 0) {
                float w = (tt < enc_lens[b]) ? __expf(s) : 0.f;
                g_aw[b * TT + tt] = w;
                if (w != 0.f) atomicAdd(&g_awsum[b], w);
            }
        }
        grid_sync(mygen);

        for (int job = gw; job < 2048; job += NWARP) {
            const int b = job >> 7;
            const int cg = (job >> 3) & 15;
            const int ts = job & 7;
            const int col = (cg << 5) + lane;
            const float inv = __fdividef(1.f, g_awsum[b]);
            const float* ao = g_aw + b * TT + ts * 64;
            const float* eo = enc_out + (size_t)b * TT * ENCD + (size_t)(ts * 64) * ENCD + col;
            float s0 = 0.f, s1 = 0.f;
            #pragma unroll 8
            for (int tt = 0; tt < 64; tt += 2) {
                s0 = fmaf(ao[tt], __ldcs(eo + (size_t)tt * ENCD), s0);
                s1 = fmaf(ao[tt + 1], __ldcs(eo + (size_t)(tt + 1) * ENCD), s1);
            }
            float cv = (s0 + s1) * inv;
            atomicAdd(&ctxw[b * ENCD + col], cv);
            atomicAdd(&g_dcat[((size_t)t * BB + b) * 1536 + 1024 + col], cv);
        }
        grid_sync(mygen);
    }
}

// ---- tiled fp32 GEMM (FFMA2). mode 0: plain; mode 3: tanh + fp16 store to g_Ah ----
#define GBM 128
#define GBN 64
#define GBK 16

__global__ __launch_bounds__(256) void gemm_kernel(
    const float* __restrict__ Am, const float* __restrict__ Bm,
    const float* __restrict__ bias, float* __restrict__ Cm,
    int M, int N, int K, int mode)
{
    __shared__ float As[GBK][GBM + 4];
    __shared__ float Bs[GBK][GBN];
    const int tid = threadIdx.x;
    const int tx = tid & 15, ty = tid >> 4;
    const int n0 = blockIdx.x * GBN;
    const int m0 = blockIdx.y * GBM;
    u64 acc2[8][2];
    #pragma unroll
    for (int r = 0; r < 8; r++) { acc2[r][0] = 0ull; acc2[r][1] = 0ull; }

    for (int k0 = 0; k0 < K; k0 += GBK) {
        #pragma unroll
        for (int i = tid; i < (GBM * GBK) / 4; i += 256) {
            int row = i >> 2, kq = (i & 3) << 2;
            float4 v = make_float4(0.f, 0.f, 0.f, 0.f);
            int gm = m0 + row;
            if (gm < M) v = *(const float4*)(Am + (size_t)gm * K + k0 + kq);
            As[kq][row] = v.x; As[kq + 1][row] = v.y; As[kq + 2][row] = v.z; As[kq + 3][row] = v.w;
        }
        {
            int row = tid >> 4, nq = (tid & 15) << 2;
            float4 v = make_float4(0.f, 0.f, 0.f, 0.f);
            if (n0 + nq < N) v = *(const float4*)(Bm + (size_t)(k0 + row) * N + n0 + nq);
            *(float4*)&Bs[row][nq] = v;
        }
        __syncthreads();
        #pragma unroll
        for (int k = 0; k < GBK; k++) {
            float4 bv = *(const float4*)&Bs[k][tx << 2];
            u64 b01 = pack2(bv.x, bv.y);
            u64 b23 = pack2(bv.z, bv.w);
            #pragma unroll
            for (int r = 0; r < 8; r++) {
                float a = As[k][(ty << 3) + r];
                u64 aa = pack2(a, a);
                fma2(acc2[r][0], aa, b01);
                fma2(acc2[r][1], aa, b23);
            }
        }
        __syncthreads();
    }
    #pragma unroll
    for (int r = 0; r < 8; r++) {
        int m = m0 + (ty << 3) + r;
        if (m >= M) continue;
        float av[4];
        unpack2(acc2[r][0], av[0], av[1]);
        unpack2(acc2[r][1], av[2], av[3]);
        #pragma unroll
        for (int c = 0; c < 4; c++) {
            int n = n0 + (tx << 2) + c;
            if (n >= N) continue;
            float v = av[c] + bias[n];
            if (mode == 3) {
                g_Ah[(size_t)m * HD + n] = __float2half(tanhf_fast(v));
            } else {
                Cm[(size_t)m * N + n] = v;
            }
        }
    }
}

// ======================= fp16 mma.sync logits GEMM (single pass) ==============
__device__ __forceinline__ uint32_t smem_u32(const void* p) {
    uint32_t a;
    asm("{ .reg .u64 t; cvta.to.shared.u64 t, %1; cvt.u32.u64 %0, t; }" : "=r"(a) : "l"(p));
    return a;
}
__device__ __forceinline__ void ldmA4(uint32_t* r, uint32_t addr) {
    asm volatile("ldmatrix.sync.aligned.m8n8.x4.shared.b16 {%0,%1,%2,%3}, [%4];"
                 : "=r"(r[0]), "=r"(r[1]), "=r"(r[2]), "=r"(r[3]) : "r"(addr));
}
__device__ __forceinline__ void ldmBT2(uint32_t* r, uint32_t addr) {
    asm volatile("ldmatrix.sync.aligned.m8n8.x2.trans.shared.b16 {%0,%1}, [%2];"
                 : "=r"(r[0]), "=r"(r[1]) : "r"(addr));
}
__device__ __forceinline__ void mma16816h(float* d, const uint32_t* a, const uint32_t* b) {
    asm volatile(
        "mma.sync.aligned.m16n8k16.row.col.f32.f16.f16.f32 "
        "{%0,%1,%2,%3}, {%4,%5,%6,%7}, {%8,%9}, {%0,%1,%2,%3};"
        : "+f"(d[0]), "+f"(d[1]), "+f"(d[2]), "+f"(d[3])
        : "r"(a[0]), "r"(a[1]), "r"(a[2]), "r"(a[3]), "r"(b[0]), "r"(b[1]));
}

#define ASTR 40   // 32 k + 8 pad
#define BSTR 72   // 64 n + 8 pad

__global__ __launch_bounds__(256) void wout_mma_kernel(const float* __restrict__ bias,
                                                       float* __restrict__ out)
{
    __shared__ __half sA[128 * ASTR];
    __shared__ __half sB[32 * BSTR];
    const int tid = threadIdx.x;
    const int lane = tid & 31;
    const int w = tid >> 5;
    const int mwarp = w & 3, nwarp = w >> 2;
    const int n0 = blockIdx.x * 64;
    const int m0 = blockIdx.y * 128;

    const uint32_t sA_b = smem_u32(sA), sB_b = smem_u32(sB);
    const uint32_t aoff = ((mwarp * 32 + (lane & 15)) * ASTR + (lane >> 4) * 8) * 2;
    const uint32_t boff = ((lane & 15) * BSTR + nwarp * 32) * 2;

    float d[2][4][4];
    #pragma unroll
    for (int mt = 0; mt < 2; ++mt)
        #pragma unroll
        for (int nt = 0; nt < 4; ++nt)
            #pragma unroll
            for (int i = 0; i < 4; ++i) d[mt][nt][i] = 0.f;

    for (int kc = 0; kc < 32; ++kc) {
        const int kb = kc * 32;
        #pragma unroll
        for (int i = tid; i < 512; i += 256) {
            const int row = i >> 2, kq = (i & 3) << 3;
            *(float4*)((char*)sA + (row * ASTR + kq) * 2) =
                *(const float4*)(g_Ah + (size_t)(m0 + row) * HD + kb + kq);
        }
        {
            const int row = tid >> 3, nq = (tid & 7) << 3;
            *(float4*)((char*)sB + (row * BSTR + nq) * 2) =
                *(const float4*)(g_Bh + (size_t)(kb + row) * NPAD + n0 + nq);
        }
        __syncthreads();

        #pragma unroll
        for (int ks = 0; ks < 2; ++ks) {
            uint32_t ah[2][4], bh[4][2];
            #pragma unroll
            for (int mt = 0; mt < 2; ++mt)
                ldmA4(ah[mt], sA_b + aoff + (mt * 16 * ASTR + ks * 16) * 2);
            #pragma unroll
            for (int nt = 0; nt < 4; ++nt)
                ldmBT2(bh[nt], sB_b + boff + (ks * 16 * BSTR + nt * 8) * 2);
            #pragma unroll
            for (int mt = 0; mt < 2; ++mt)
                #pragma unroll
                for (int nt = 0; nt < 4; ++nt)
                    mma16816h(d[mt][nt], ah[mt], bh[nt]);
        }
        __syncthreads();
    }

    const int grp = lane >> 2, tig = lane & 3;
    #pragma unroll
    for (int mt = 0; mt < 2; ++mt) {
        #pragma unroll
        for (int rr = 0; rr < 2; ++rr) {
            const int m = m0 + mwarp * 32 + mt * 16 + grp + rr * 8;
            if (m >= NSTEP * BB) continue;
            const int bb = m & 15, tt = m >> 4;
            float* orow = out + ((size_t)bb * NSTEP + tt) * VD;
            #pragma unroll
            for (int nt = 0; nt < 4; ++nt) {
                const int n = n0 + nwarp * 32 + nt * 8 + tig * 2;
                if (n < VD) {
                    orow[n] = d[mt][nt][rr * 2 + 0] + bias[n];
                    orow[n + 1] = d[mt][nt][rr * 2 + 1] + bias[n + 1];
                }
            }
        }
    }
}

extern "C" void kernel_launch(void* const* d_in, const int* in_sizes, int n_in,
                              void* d_out, int out_size)
{
    const float* enc_out  = (const float*)d_in[0];
    const int*   enc_lens = (const int*)d_in[1];
    const int*   ys       = (const int*)d_in[2];
    const float* embed    = (const float*)d_in[3];
    const float* Wih0     = (const float*)d_in[4];
    const float* Whh0     = (const float*)d_in[5];
    const float* b0       = (const float*)d_in[6];
    const float* Wih1     = (const float*)d_in[7];
    const float* Whh1     = (const float*)d_in[8];
    const float* b1       = (const float*)d_in[9];
    const float* W_enc    = (const float*)d_in[10];
    const float* b_att    = (const float*)d_in[11];
    const float* v_att    = (const float*)d_in[12];
    const float* W_dec    = (const float*)d_in[13];
    const float* W_bn     = (const float*)d_in[14];
    const float* b_bn     = (const float*)d_in[15];
    const float* W_out    = (const float*)d_in[16];
    const float* b_out    = (const float*)d_in[17];
    float* out = (float*)d_out;

    float *p_encproj, *p_dcat;
    cudaGetSymbolAddress((void**)&p_encproj, g_encproj);
    cudaGetSymbolAddress((void**)&p_dcat, g_dcat);

    init_kernel<<<(BB * HD + 255) / 256, 256>>>();

    {
        size_t tot = (size_t)HD * NPAD;
        conv_all_kernel<<<(unsigned)((tot + 255) / 256), 256>>>(Wih0, Whh0, Wih1, Whh1, W_out);
    }

    {
        dim3 grid(AD / GBN, (BB * TT + GBM - 1) / GBM);
        gemm_kernel<<<grid, 256>>>(enc_out, W_enc, b_att, p_encproj, BB * TT, AD, ENCD, 0);
    }

    dec_persistent<<<NBLK, NTHR>>>(enc_out, enc_lens, ys, embed, b0, b1, W_dec, v_att);

    {
        dim3 grid(HD / GBN, (NSTEP * BB + GBM - 1) / GBM);
        gemm_kernel<<<grid, 256>>>(p_dcat, W_bn, b_bn, p_dcat /*unused*/, NSTEP * BB, HD, 1536, 3);
    }

    {
        dim3 grid(NPAD / 64, MROWS / 128);
        wout_mma_kernel<<<grid, 256>>>(b_out, out);
    }
    (void)in_sizes; (void)n_in; (void)out_size;
}

// round 16
// speedup vs baseline: 2.3769x; 1.0888x over previous
#include <cuda_runtime.h>
#include <cuda_bf16.h>
#include <cuda_fp16.h>
#include <cstdint>

#define BB 16
#define TT 512
#define LL 128
#define NSTEP 129
#define ENCD 512
#define HD 1024
#define ED 512
#define VD 10000
#define AD 512

#define NBLK 148
#define NTHR 512
#define NWARP (NBLK * (NTHR / 32))

typedef unsigned long long u64;

// ---- scratch (device globals; allocs are forbidden) ----
__device__ float g_encproj[(size_t)BB * TT * AD];
__device__ float g_h0[2][BB * HD];
__device__ float g_h1[2][BB * HD];
__device__ float g_c0[BB * HD];
__device__ float g_c1[BB * HD];
__device__ float g_ctx[2][BB * ENCD];
__device__ float g_dproj[BB * AD];
__device__ float g_aw[BB * TT];
__device__ float g_awsum[BB];
__device__ float g_dcat[(size_t)NSTEP * BB * 1536];
__device__ unsigned g_bar;
__device__ volatile unsigned g_gen;

// fp16 LSTM weights (L2-resident working set)
#define WSZ ((size_t)4096 * 1024)
__device__ __half g_Wih0h[WSZ];
__device__ __half g_Whh0h[WSZ];
__device__ __half g_Wih1h[WSZ];
__device__ __half g_Whh1h[WSZ];

// fp16 buffers for tensor-core logits GEMM
#define MROWS 2176
#define NPAD 10048
__device__ __half g_Ah[(size_t)MROWS * HD];   // [m][k]
__device__ __half g_Bh[(size_t)HD * NPAD];    // [k][n]

__device__ __forceinline__ float sigf(float x) { return __fdividef(1.f, 1.f + __expf(-x)); }
__device__ __forceinline__ float tanhf_fast(float x) {
    float z = __expf(2.f * x);
    return 1.f - __fdividef(2.f, z + 1.f);
}
__device__ __forceinline__ float tanh_apx(float x) {
    float r; asm("tanh.approx.f32 %0, %1;" : "=f"(r) : "f"(x)); return r;
}

// packed f32x2 helpers (fp32 GEMM only)
__device__ __forceinline__ void fma2(u64& acc, u64 a, u64 b) {
    asm("fma.rn.f32x2 %0, %1, %2, %0;" : "+l"(acc) : "l"(a), "l"(b));
}
__device__ __forceinline__ u64 pack2(float lo, float hi) {
    u64 r; asm("mov.b64 %0, {%1, %2};" : "=l"(r) : "f"(lo), "f"(hi)); return r;
}
__device__ __forceinline__ void unpack2(u64 v, float& lo, float& hi) {
    asm("mov.b64 {%0, %1}, %2;" : "=f"(lo), "=f"(hi) : "l"(v));
}

__device__ __forceinline__ float4 h2f4(uint2 v) {
    float2 f0 = __half22float2(*(__half2*)&v.x);
    float2 f1 = __half22float2(*(__half2*)&v.y);
    return make_float4(f0.x, f0.y, f1.x, f1.y);
}

// R5-proven barrier
__device__ __forceinline__ void grid_sync(unsigned& mygen) {
    __syncthreads();
    if (threadIdx.x == 0) {
        unsigned tgt = mygen + 1u;
        __threadfence();
        if (atomicAdd(&g_bar, 1u) == NBLK - 1) {
            g_bar = 0u;
            __threadfence();
            g_gen = tgt;
        } else {
            while (g_gen < tgt) { __nanosleep(64); }
            __threadfence();
        }
    }
    mygen += 1u;
    __syncthreads();
}

#define DOT4(S, X, W) \
    S = fmaf((X).x, (W).x, S); S = fmaf((X).y, (W).y, S); \
    S = fmaf((X).z, (W).z, S); S = fmaf((X).w, (W).w, S);

#define RSTAGE(OFF, HALF) \
    { bool hi = (lane & OFF) != 0; \
      _Pragma("unroll") \
      for (int i = 0; i < HALF; ++i) { \
          float o0 = __shfl_xor_sync(0xffffffffu, acc[i], OFF); \
          float o1 = __shfl_xor_sync(0xffffffffu, acc[i + HALF], OFF); \
          acc[i] = hi ? (acc[i + HALF] + o1) : (acc[i] + o0); \
      } }

__global__ void init_kernel() {
    int i = blockIdx.x * blockDim.x + threadIdx.x;
    if (i < BB * HD) { g_h0[0][i] = 0.f; g_c0[i] = 0.f; g_h1[0][i] = 0.f; g_c1[i] = 0.f; }
    if (i < BB * ENCD) g_ctx[0][i] = 0.f;
    if (i == 0) { g_bar = 0u; g_gen = 0u; }
    for (size_t j = i; j < (size_t)(MROWS - 2064) * HD; j += (size_t)16384)
        g_Ah[(size_t)2064 * HD + j] = __float2half(0.f);
}

// merged converters
__global__ void conv_all_kernel(const float* __restrict__ W0, const float* __restrict__ W1,
                                const float* __restrict__ W2, const float* __restrict__ W3,
                                const float* __restrict__ Wout) {
    size_t i = (size_t)blockIdx.x * blockDim.x + threadIdx.x;
    if (i < WSZ) {
        g_Wih0h[i] = __float2half(W0[i]);
        g_Whh0h[i] = __float2half(W1[i]);
        g_Wih1h[i] = __float2half(W2[i]);
        g_Whh1h[i] = __float2half(W3[i]);
    }
    if (i < (size_t)HD * NPAD) {
        int n = (int)(i % NPAD);
        float v = (n < VD) ? Wout[(size_t)(i / NPAD) * VD + n] : 0.f;
        g_Bh[i] = __float2half(v);
    }
}

// ======================= persistent recurrent kernel =========================
// Jobs: 2048 = 1024 units x 2 batch-groups of 8. 16 unified rounds with explicit
// one-round-ahead weight prefetch (L2 latency hidden behind 128-FMA round body).
template<int LAYER>
__device__ __forceinline__ void lstm_pass(
    int t, int gw, int lane,
    const int* __restrict__ ys, const float* __restrict__ embed,
    const __half* __restrict__ Wih, const __half* __restrict__ Whh,
    const float* __restrict__ bi,
    const float* __restrict__ ctx,
    const float* __restrict__ hprev,
    const float* __restrict__ h0new,
    float* __restrict__ cbuf, float* __restrict__ hout)
{
    for (int j = gw; j < 2048; j += NWARP) {
        const int u = j >> 1;
        const int b0 = (j & 1) << 3;
        int tok[8];
        if (LAYER == 0) {
            #pragma unroll
            for (int b = 0; b < 8; ++b)
                tok[b] = (t == 0) ? 1 : ys[(b0 + b) * LL + (t - 1)];
        }
        float acc[32];
        #pragma unroll
        for (int i = 0; i < 32; ++i) acc[i] = 0.f;

        // weight pointer for round r, gate g (r: 0..7 = ih, 8..15 = hh)
        const int lk = lane * 4;
        uint2 wn[4];
        #pragma unroll
        for (int g = 0; g < 4; ++g)
            wn[g] = __ldcg((const uint2*)(Wih + (size_t)(u + g * HD) * 1024 + lk));

        #pragma unroll
        for (int r = 0; r < 16; ++r) {
            uint2 wc[4];
            #pragma unroll
            for (int g = 0; g < 4; ++g) wc[g] = wn[g];
            if (r < 15) {
                const __half* Wn = (r + 1 < 8) ? Wih : Whh;
                const int kn = ((r + 1) & 7) * 128 + lk;
                #pragma unroll
                for (int g = 0; g < 4; ++g)
                    wn[g] = __ldcg((const uint2*)(Wn + (size_t)(u + g * HD) * 1024 + kn));
            }
            // x loads for this round
            float4 xr[8];
            #pragma unroll
            for (int b = 0; b < 8; ++b) {
                const float* px;
                if (LAYER == 0) {
                    if (r < 4)       px = embed + (size_t)tok[b] * ED + r * 128 + lk;
                    else if (r < 8)  px = ctx + (b0 + b) * ENCD + (r - 4) * 128 + lk;
                    else             px = hprev + (b0 + b) * HD + (r - 8) * 128 + lk;
                } else {
                    if (r < 8)       px = h0new + (b0 + b) * HD + r * 128 + lk;
                    else             px = hprev + (b0 + b) * HD + (r - 8) * 128 + lk;
                }
                xr[b] = *(const float4*)px;
            }
            #pragma unroll
            for (int g = 0; g < 4; ++g) {
                float4 w = h2f4(wc[g]);
                #pragma unroll
                for (int b = 0; b < 8; ++b) { DOT4(acc[g * 8 + b], xr[b], w); }
            }
        }

        RSTAGE(16, 16) RSTAGE(8, 8) RSTAGE(4, 4) RSTAGE(2, 2) RSTAGE(1, 1)
        float v = acc[0];
        float sf = __shfl_sync(0xffffffffu, v, (lane & 7) + 8);
        float sg = __shfl_sync(0xffffffffu, v, (lane & 7) + 16);
        float so = __shfl_sync(0xffffffffu, v, (lane & 7) + 24);
        if (lane < 8) {
            const int b = b0 + lane;
            const int idx = b * HD + u;
            float si_ = v + bi[u];
            float sf_ = sf + bi[u + HD];
            float sg_ = sg + bi[u + 2 * HD];
            float so_ = so + bi[u + 3 * HD];
            float c = sigf(sf_) * cbuf[idx] + sigf(si_) * tanhf_fast(sg_);
            cbuf[idx] = c;
            float h = sigf(so_) * tanhf_fast(c);
            hout[idx] = h;
            if (LAYER == 1)
                g_dcat[((size_t)t * BB + b) * 1536 + u] = h + h0new[idx];
        }
    }
}

__global__ __launch_bounds__(NTHR, 1) void dec_persistent(
    const float* __restrict__ enc_out, const int* __restrict__ enc_lens,
    const int* __restrict__ ys, const float* __restrict__ embed,
    const float* __restrict__ bi0, const float* __restrict__ bi1,
    const float* __restrict__ Wdec, const float* __restrict__ vatt)
{
    const int lane = threadIdx.x & 31;
    const int gw = blockIdx.x * (NTHR / 32) + (threadIdx.x >> 5);
    const int gt = blockIdx.x * NTHR + threadIdx.x;
    unsigned mygen = 0;

    for (int t = 0; t < NSTEP; ++t) {
        const int par = t & 1;
        const float* h0r = g_h0[par];
        float* h0w = g_h0[par ^ 1];
        const float* h1r = g_h1[par];
        float* h1w = g_h1[par ^ 1];
        const float* ctxr = g_ctx[par];
        float* ctxw = g_ctx[par ^ 1];

        lstm_pass<0>(t, gw, lane, ys, embed, g_Wih0h, g_Whh0h, bi0, ctxr, h0r, h0w, g_c0, h0w);
        if (gt < BB * AD) g_dproj[gt] = 0.f;
        grid_sync(mygen);

        lstm_pass<1>(t, gw, lane, ys, embed, g_Wih1h, g_Whh1h, bi1, ctxr, h1r, h0w, g_c1, h1w);
        if (gt < BB * ENCD) {
            ctxw[gt] = 0.f;
            g_dcat[((size_t)t * BB + (gt >> 9)) * 1536 + 1024 + (gt & 511)] = 0.f;
        }
        if (gt < BB) g_awsum[gt] = 0.f;
        grid_sync(mygen);

        for (int job = gw; job < 2048; job += NWARP) {
            const int b = job >> 7;
            const int cg = (job >> 3) & 15;
            const int ks = job & 7;
            const int a0 = cg << 5;
            const float* dec = g_dcat + ((size_t)t * BB + b) * 1536 + ks * 128;
            const float* w = Wdec + (size_t)(ks * 128) * AD + a0 + lane;
            float s0 = 0.f, s1 = 0.f, s2 = 0.f, s3 = 0.f;
            #pragma unroll 8
            for (int k = 0; k < 128; k += 4) {
                s0 = fmaf(dec[k], w[(size_t)k * AD], s0);
                s1 = fmaf(dec[k + 1], w[(size_t)(k + 1) * AD], s1);
                s2 = fmaf(dec[k + 2], w[(size_t)(k + 2) * AD], s2);
                s3 = fmaf(dec[k + 3], w[(size_t)(k + 3) * AD], s3);
            }
            atomicAdd(&g_dproj[b * AD + a0 + lane], (s0 + s1) + (s2 + s3));
        }
        grid_sync(mygen);

        for (int job = gw; job < BB * TT; job += NWARP) {
            const int b = job >> 9, tt = job & (TT - 1);
            const float4* p4 = (const float4*)(g_encproj + (size_t)(b * TT + tt) * AD);
            const float4* d4 = (const float4*)(g_dproj + b * AD);
            const float4* v4 = (const float4*)vatt;
            float s = 0.f;
            #pragma unroll
            for (int i = lane; i < AD / 4; i += 32) {
                float4 p = __ldcs(p4 + i); float4 d = d4[i]; float4 vv = v4[i];
                s = fmaf(vv.x, tanh_apx(p.x + d.x), s);
                s = fmaf(vv.y, tanh_apx(p.y + d.y), s);
                s = fmaf(vv.z, tanh_apx(p.z + d.z), s);
                s = fmaf(vv.w, tanh_apx(p.w + d.w), s);
            }
            #pragma unroll
            for (int off = 16; off > 0; off >>= 1) s += __shfl_xor_sync(0xffffffffu, s, off);
            if (lane == 0) {
                float w = (tt < enc_lens[b]) ? __expf(s) : 0.f;
                g_aw[b * TT + tt] = w;
                if (w != 0.f) atomicAdd(&g_awsum[b], w);
            }
        }
        grid_sync(mygen);

        for (int job = gw; job < 2048; job += NWARP) {
            const int b = job >> 7;
            const int cg = (job >> 3) & 15;
            const int ts = job & 7;
            const int col = (cg << 5) + lane;
            const float inv = __fdividef(1.f, g_awsum[b]);
            const float* ao = g_aw + b * TT + ts * 64;
            const float* eo = enc_out + (size_t)b * TT * ENCD + (size_t)(ts * 64) * ENCD + col;
            float s0 = 0.f, s1 = 0.f;
            #pragma unroll 8
            for (int tt = 0; tt < 64; tt += 2) {
                s0 = fmaf(ao[tt], __ldcs(eo + (size_t)tt * ENCD), s0);
                s1 = fmaf(ao[tt + 1], __ldcs(eo + (size_t)(tt + 1) * ENCD), s1);
            }
            float cv = (s0 + s1) * inv;
            atomicAdd(&ctxw[b * ENCD + col], cv);
            atomicAdd(&g_dcat[((size_t)t * BB + b) * 1536 + 1024 + col], cv);
        }
        grid_sync(mygen);
    }
}

// ---- tiled fp32 GEMM (FFMA2). mode 0: plain; mode 3: tanh + fp16 store to g_Ah ----
#define GBM 128
#define GBN 64
#define GBK 16

__global__ __launch_bounds__(256) void gemm_kernel(
    const float* __restrict__ Am, const float* __restrict__ Bm,
    const float* __restrict__ bias, float* __restrict__ Cm,
    int M, int N, int K, int mode)
{
    __shared__ float As[GBK][GBM + 4];
    __shared__ float Bs[GBK][GBN];
    const int tid = threadIdx.x;
    const int tx = tid & 15, ty = tid >> 4;
    const int n0 = blockIdx.x * GBN;
    const int m0 = blockIdx.y * GBM;
    u64 acc2[8][2];
    #pragma unroll
    for (int r = 0; r < 8; r++) { acc2[r][0] = 0ull; acc2[r][1] = 0ull; }

    for (int k0 = 0; k0 < K; k0 += GBK) {
        #pragma unroll
        for (int i = tid; i < (GBM * GBK) / 4; i += 256) {
            int row = i >> 2, kq = (i & 3) << 2;
            float4 v = make_float4(0.f, 0.f, 0.f, 0.f);
            int gm = m0 + row;
            if (gm < M) v = *(const float4*)(Am + (size_t)gm * K + k0 + kq);
            As[kq][row] = v.x; As[kq + 1][row] = v.y; As[kq + 2][row] = v.z; As[kq + 3][row] = v.w;
        }
        {
            int row = tid >> 4, nq = (tid & 15) << 2;
            float4 v = make_float4(0.f, 0.f, 0.f, 0.f);
            if (n0 + nq < N) v = *(const float4*)(Bm + (size_t)(k0 + row) * N + n0 + nq);
            *(float4*)&Bs[row][nq] = v;
        }
        __syncthreads();
        #pragma unroll
        for (int k = 0; k < GBK; k++) {
            float4 bv = *(const float4*)&Bs[k][tx << 2];
            u64 b01 = pack2(bv.x, bv.y);
            u64 b23 = pack2(bv.z, bv.w);
            #pragma unroll
            for (int r = 0; r < 8; r++) {
                float a = As[k][(ty << 3) + r];
                u64 aa = pack2(a, a);
                fma2(acc2[r][0], aa, b01);
                fma2(acc2[r][1], aa, b23);
            }
        }
        __syncthreads();
    }
    #pragma unroll
    for (int r = 0; r < 8; r++) {
        int m = m0 + (ty << 3) + r;
        if (m >= M) continue;
        float av[4];
        unpack2(acc2[r][0], av[0], av[1]);
        unpack2(acc2[r][1], av[2], av[3]);
        #pragma unroll
        for (int c = 0; c < 4; c++) {
            int n = n0 + (tx << 2) + c;
            if (n >= N) continue;
            float v = av[c] + bias[n];
            if (mode == 3) {
                g_Ah[(size_t)m * HD + n] = __float2half(tanhf_fast(v));
            } else {
                Cm[(size_t)m * N + n] = v;
            }
        }
    }
}

// ======================= fp16 mma.sync logits GEMM (single pass) ==============
__device__ __forceinline__ uint32_t smem_u32(const void* p) {
    uint32_t a;
    asm("{ .reg .u64 t; cvta.to.shared.u64 t, %1; cvt.u32.u64 %0, t; }" : "=r"(a) : "l"(p));
    return a;
}
__device__ __forceinline__ void ldmA4(uint32_t* r, uint32_t addr) {
    asm volatile("ldmatrix.sync.aligned.m8n8.x4.shared.b16 {%0,%1,%2,%3}, [%4];"
                 : "=r"(r[0]), "=r"(r[1]), "=r"(r[2]), "=r"(r[3]) : "r"(addr));
}
__device__ __forceinline__ void ldmBT2(uint32_t* r, uint32_t addr) {
    asm volatile("ldmatrix.sync.aligned.m8n8.x2.trans.shared.b16 {%0,%1}, [%2];"
                 : "=r"(r[0]), "=r"(r[1]) : "r"(addr));
}
__device__ __forceinline__ void mma16816h(float* d, const uint32_t* a, const uint32_t* b) {
    asm volatile(
        "mma.sync.aligned.m16n8k16.row.col.f32.f16.f16.f32 "
        "{%0,%1,%2,%3}, {%4,%5,%6,%7}, {%8,%9}, {%0,%1,%2,%3};"
        : "+f"(d[0]), "+f"(d[1]), "+f"(d[2]), "+f"(d[3])
        : "r"(a[0]), "r"(a[1]), "r"(a[2]), "r"(a[3]), "r"(b[0]), "r"(b[1]));
}

#define ASTR 40
#define BSTR 72

__global__ __launch_bounds__(256) void wout_mma_kernel(const float* __restrict__ bias,
                                                       float* __restrict__ out)
{
    __shared__ __half sA[128 * ASTR];
    __shared__ __half sB[32 * BSTR];
    const int tid = threadIdx.x;
    const int lane = tid & 31;
    const int w = tid >> 5;
    const int mwarp = w & 3, nwarp = w >> 2;
    const int n0 = blockIdx.x * 64;
    const int m0 = blockIdx.y * 128;

    const uint32_t sA_b = smem_u32(sA), sB_b = smem_u32(sB);
    const uint32_t aoff = ((mwarp * 32 + (lane & 15)) * ASTR + (lane >> 4) * 8) * 2;
    const uint32_t boff = ((lane & 15) * BSTR + nwarp * 32) * 2;

    float d[2][4][4];
    #pragma unroll
    for (int mt = 0; mt < 2; ++mt)
        #pragma unroll
        for (int nt = 0; nt < 4; ++nt)
            #pragma unroll
            for (int i = 0; i < 4; ++i) d[mt][nt][i] = 0.f;

    for (int kc = 0; kc < 32; ++kc) {
        const int kb = kc * 32;
        #pragma unroll
        for (int i = tid; i < 512; i += 256) {
            const int row = i >> 2, kq = (i & 3) << 3;
            *(float4*)((char*)sA + (row * ASTR + kq) * 2) =
                *(const float4*)(g_Ah + (size_t)(m0 + row) * HD + kb + kq);
        }
        {
            const int row = tid >> 3, nq = (tid & 7) << 3;
            *(float4*)((char*)sB + (row * BSTR + nq) * 2) =
                *(const float4*)(g_Bh + (size_t)(kb + row) * NPAD + n0 + nq);
        }
        __syncthreads();

        #pragma unroll
        for (int ks = 0; ks < 2; ++ks) {
            uint32_t ah[2][4], bh[4][2];
            #pragma unroll
            for (int mt = 0; mt < 2; ++mt)
                ldmA4(ah[mt], sA_b + aoff + (mt * 16 * ASTR + ks * 16) * 2);
            #pragma unroll
            for (int nt = 0; nt < 4; ++nt)
                ldmBT2(bh[nt], sB_b + boff + (ks * 16 * BSTR + nt * 8) * 2);
            #pragma unroll
            for (int mt = 0; mt < 2; ++mt)
                #pragma unroll
                for (int nt = 0; nt < 4; ++nt)
                    mma16816h(d[mt][nt], ah[mt], bh[nt]);
        }
        __syncthreads();
    }

    const int grp = lane >> 2, tig = lane & 3;
    #pragma unroll
    for (int mt = 0; mt < 2; ++mt) {
        #pragma unroll
        for (int rr = 0; rr < 2; ++rr) {
            const int m = m0 + mwarp * 32 + mt * 16 + grp + rr * 8;
            if (m >= NSTEP * BB) continue;
            const int bb = m & 15, tt = m >> 4;
            float* orow = out + ((size_t)bb * NSTEP + tt) * VD;
            #pragma unroll
            for (int nt = 0; nt < 4; ++nt) {
                const int n = n0 + nwarp * 32 + nt * 8 + tig * 2;
                if (n < VD) {
                    orow[n] = d[mt][nt][rr * 2 + 0] + bias[n];
                    orow[n + 1] = d[mt][nt][rr * 2 + 1] + bias[n + 1];
                }
            }
        }
    }
}

extern "C" void kernel_launch(void* const* d_in, const int* in_sizes, int n_in,
                              void* d_out, int out_size)
{
    const float* enc_out  = (const float*)d_in[0];
    const int*   enc_lens = (const int*)d_in[1];
    const int*   ys       = (const int*)d_in[2];
    const float* embed    = (const float*)d_in[3];
    const float* Wih0     = (const float*)d_in[4];
    const float* Whh0     = (const float*)d_in[5];
    const float* b0       = (const float*)d_in[6];
    const float* Wih1     = (const float*)d_in[7];
    const float* Whh1     = (const float*)d_in[8];
    const float* b1       = (const float*)d_in[9];
    const float* W_enc    = (const float*)d_in[10];
    const float* b_att    = (const float*)d_in[11];
    const float* v_att    = (const float*)d_in[12];
    const float* W_dec    = (const float*)d_in[13];
    const float* W_bn     = (const float*)d_in[14];
    const float* b_bn     = (const float*)d_in[15];
    const float* W_out    = (const float*)d_in[16];
    const float* b_out    = (const float*)d_in[17];
    float* out = (float*)d_out;

    float *p_encproj, *p_dcat;
    cudaGetSymbolAddress((void**)&p_encproj, g_encproj);
    cudaGetSymbolAddress((void**)&p_dcat, g_dcat);

    init_kernel<<<(BB * HD + 255) / 256, 256>>>();

    {
        size_t tot = (size_t)HD * NPAD;
        conv_all_kernel<<<(unsigned)((tot + 255) / 256), 256>>>(Wih0, Whh0, Wih1, Whh1, W_out);
    }

    {
        dim3 grid(AD / GBN, (BB * TT + GBM - 1) / GBM);
        gemm_kernel<<<grid, 256>>>(enc_out, W_enc, b_att, p_encproj, BB * TT, AD, ENCD, 0);
    }

    dec_persistent<<<NBLK, NTHR>>>(enc_out, enc_lens, ys, embed, b0, b1, W_dec, v_att);

    {
        dim3 grid(HD / GBN, (NSTEP * BB + GBM - 1) / GBM);
        gemm_kernel<<<grid, 256>>>(p_dcat, W_bn, b_bn, p_dcat /*unused*/, NSTEP * BB, HD, 1536, 3);
    }

    {
        dim3 grid(NPAD / 64, MROWS / 128);
        wout_mma_kernel<<<grid, 256>>>(b_out, out);
    }
    (void)in_sizes; (void)n_in; (void)out_size;
}